// round 1
// baseline (speedup 1.0000x reference)
#include <cuda_runtime.h>

#define NTOK  1024
#define DS    384
#define DP    128
#define NH    16
#define DH    64
#define INNER 1024
#define NN    (NTOK*NTOK)

// ---------------- scratch (device globals; no allocation allowed) ----------------
__device__ float g_q[NTOK*INNER];
__device__ float g_k[NTOK*INNER];
__device__ float g_v[NTOK*INNER];
__device__ float g_g[NTOK*INNER];
__device__ float g_scores[(size_t)NH*NN];     // 64 MB: bias + attn_bias (pre-qk)
__device__ float g_attnout[NTOK*INNER];       // [i][h*64+d]
__device__ float g_gw[NH*DP];                 // [h][d] = gamma[d]*Wb[d][h]
__device__ float g_T[NH];                     // sum_d gamma[d]*Wb[d][h]
__device__ float g_U[NH];                     // sum_d beta[d]*Wb[d][h]

// ---------------- K0: tiny precompute ----------------
__global__ void prep_kernel(const float* __restrict__ gamma,
                            const float* __restrict__ beta,
                            const float* __restrict__ Wb)
{
    int t = threadIdx.x;
    for (int l = t; l < NH*DP; l += blockDim.x) {
        int h = l / DP, d = l % DP;
        g_gw[h*DP + d] = gamma[d] * Wb[d*NH + h];
    }
    if (t < 2*NH) {
        int h = t % NH;
        const float* src = (t < NH) ? gamma : beta;
        float s = 0.f;
        for (int d = 0; d < DP; d++) s += src[d] * Wb[d*NH + h];
        if (t < NH) g_T[h] = s; else g_U[h] = s;
    }
}

// ---------------- K1: projections  C[i][f] = X[i]·W[:,f] (+bq for q) ----------------
// X:[1024,384]  W:[384,1024]  -> 4 outputs selected by blockIdx.z
#define P_BM 128
#define P_BN 64
#define P_BK 16
__global__ __launch_bounds__(256) void proj_kernel(
    const float* __restrict__ X,
    const float* __restrict__ Wq, const float* __restrict__ bq,
    const float* __restrict__ Wk, const float* __restrict__ Wv,
    const float* __restrict__ Wg)
{
    __shared__ __align__(16) float As[P_BK][P_BM];
    __shared__ __align__(16) float Bs[P_BK][P_BN];

    int sel = blockIdx.z;
    const float* W = (sel==0) ? Wq : (sel==1) ? Wk : (sel==2) ? Wv : Wg;
    float* out     = (sel==0) ? g_q : (sel==1) ? g_k : (sel==2) ? g_v : g_g;

    int t  = threadIdx.x;
    int tx = t & 15;   // n dir
    int ty = t >> 4;   // m dir
    int m0 = blockIdx.y * P_BM;
    int n0 = blockIdx.x * P_BN;

    float acc[8][4];
    #pragma unroll
    for (int i = 0; i < 8; i++)
        #pragma unroll
        for (int j = 0; j < 4; j++) acc[i][j] = 0.f;

    for (int k0 = 0; k0 < DS; k0 += P_BK) {
        #pragma unroll
        for (int r = 0; r < 2; r++) {
            int s  = t + 256*r;
            int m  = s >> 2;
            int kq = (s & 3) * 4;
            float4 xv = *(const float4*)(X + (m0+m)*DS + k0 + kq);
            As[kq+0][m] = xv.x; As[kq+1][m] = xv.y;
            As[kq+2][m] = xv.z; As[kq+3][m] = xv.w;
        }
        {
            int k = t >> 4;
            int n = (t & 15) * 4;
            *(float4*)&Bs[k][n] = *(const float4*)(W + (k0+k)*INNER + n0 + n);
        }
        __syncthreads();
        #pragma unroll
        for (int k = 0; k < P_BK; k++) {
            float a[8], b[4];
            #pragma unroll
            for (int i = 0; i < 8; i++) a[i] = As[k][ty*8 + i];
            #pragma unroll
            for (int j = 0; j < 4; j++) b[j] = Bs[k][tx*4 + j];
            #pragma unroll
            for (int i = 0; i < 8; i++)
                #pragma unroll
                for (int j = 0; j < 4; j++)
                    acc[i][j] += a[i] * b[j];
        }
        __syncthreads();
    }
    float4 bqv = make_float4(0.f, 0.f, 0.f, 0.f);
    if (sel == 0) bqv = *(const float4*)(bq + n0 + tx*4);
    #pragma unroll
    for (int i = 0; i < 8; i++) {
        int m = m0 + ty*8 + i;
        float4 c;
        c.x = acc[i][0] + bqv.x; c.y = acc[i][1] + bqv.y;
        c.z = acc[i][2] + bqv.z; c.w = acc[i][3] + bqv.w;
        *(float4*)(out + (size_t)m*INNER + n0 + tx*4) = c;
    }
}

// ---------------- K2: fused LN + pw@ (gamma*Wb) + attn_bias -> g_scores ----------------
// bias_h(p) = rinv*(A_h - mu*T_h) + U_h + attn_bias[p];  A_h = sum_d pw[p][d]*gW[h][d]
__global__ __launch_bounds__(256) void bias_kernel(
    const float* __restrict__ pw, const float* __restrict__ ab)
{
    __shared__ __align__(16) float gWs[NH][DP];
    __shared__ float Ts[NH], Us[NH];
    int t = threadIdx.x;
    for (int l = t; l < NH*DP; l += 256) ((float*)gWs)[l] = g_gw[l];
    if (t < NH)      Ts[t] = g_T[t];
    else if (t < 2*NH) Us[t-NH] = g_U[t-NH];
    __syncthreads();

    size_t p = (size_t)blockIdx.x * 256 + t;
    const float* x = pw + p * DP;

    float acc[NH];
    #pragma unroll
    for (int h = 0; h < NH; h++) acc[h] = 0.f;
    float sum = 0.f, ssq = 0.f;

    #pragma unroll 4
    for (int d = 0; d < DP; d += 4) {
        float4 xv = *(const float4*)(x + d);
        sum += xv.x + xv.y + xv.z + xv.w;
        ssq += xv.x*xv.x; ssq += xv.y*xv.y; ssq += xv.z*xv.z; ssq += xv.w*xv.w;
        #pragma unroll
        for (int h = 0; h < NH; h++) {
            float4 w = *(const float4*)&gWs[h][d];
            acc[h] += xv.x*w.x + xv.y*w.y + xv.z*w.z + xv.w*w.w;
        }
    }
    float mu   = sum * (1.f/DP);
    float var  = ssq * (1.f/DP) - mu*mu;
    float rinv = rsqrtf(var + 1e-5f);
    float abp  = ab[p];
    #pragma unroll
    for (int h = 0; h < NH; h++) {
        g_scores[(size_t)h*NN + p] = rinv*(acc[h] - mu*Ts[h]) + Us[h] + abp;
    }
}

// ---------------- K3: per (h, 16 rows): qk*scale + bias, softmax, P@V ----------------
// dynamic smem: Ps[16][1024] | Ts[64*65] (K chunk transposed / V chunk) | qs[16][64] | rinv[16]
__global__ __launch_bounds__(256) void attn_kernel()
{
    extern __shared__ float sm[];
    float* Ps   = sm;                    // 16*1024
    float* Ts   = Ps + 16*1024;          // 64*65
    float* qs   = Ts + 64*65;            // 16*64
    float* rinv = qs + 16*64;            // 16

    int t  = threadIdx.x;
    int h  = blockIdx.y;
    int i0 = blockIdx.x * 16;

    for (int l = t; l < 16*64; l += 256) {
        int r = l >> 6, d = l & 63;
        qs[l] = g_q[(size_t)(i0+r)*INNER + h*DH + d];
    }

    int r4 = t >> 6;     // 0..3 -> rows r4*4 .. r4*4+3
    int jl = t & 63;
    const float scale = 0.125f;          // dh^-0.5

    // ---- phase 1: scores tile = q·k*scale + g_scores ----
    for (int jc = 0; jc < NTOK; jc += 64) {
        // stage K chunk transposed: Ts[d*65 + j]
        for (int l = t; l < 64*64; l += 256) {
            int j = l >> 6, d = l & 63;
            Ts[d*65 + j] = g_k[(size_t)(jc+j)*INNER + h*DH + d];
        }
        __syncthreads();
        float a0=0.f, a1=0.f, a2=0.f, a3=0.f;
        const float* q0 = qs + (r4*4+0)*64;
        const float* q1 = qs + (r4*4+1)*64;
        const float* q2 = qs + (r4*4+2)*64;
        const float* q3 = qs + (r4*4+3)*64;
        #pragma unroll 8
        for (int d = 0; d < 64; d++) {
            float kv = Ts[d*65 + jl];
            a0 += q0[d]*kv; a1 += q1[d]*kv; a2 += q2[d]*kv; a3 += q3[d]*kv;
        }
        size_t sb = (size_t)h*NN + (size_t)i0*NTOK + jc + jl;
        Ps[(r4*4+0)*1024 + jc + jl] = a0*scale + g_scores[sb + (size_t)(r4*4+0)*NTOK];
        Ps[(r4*4+1)*1024 + jc + jl] = a1*scale + g_scores[sb + (size_t)(r4*4+1)*NTOK];
        Ps[(r4*4+2)*1024 + jc + jl] = a2*scale + g_scores[sb + (size_t)(r4*4+2)*NTOK];
        Ps[(r4*4+3)*1024 + jc + jl] = a3*scale + g_scores[sb + (size_t)(r4*4+3)*NTOK];
        __syncthreads();
    }

    // ---- phase 2: softmax per row (warp per 2 rows) ----
    int wid = t >> 5, lane = t & 31;
    #pragma unroll
    for (int rr = 0; rr < 2; rr++) {
        int row = wid*2 + rr;
        float m = -1e30f;
        for (int l = lane; l < 1024; l += 32) m = fmaxf(m, Ps[row*1024 + l]);
        #pragma unroll
        for (int o = 16; o; o >>= 1) m = fmaxf(m, __shfl_xor_sync(0xffffffffu, m, o));
        float s = 0.f;
        for (int l = lane; l < 1024; l += 32) {
            float e = __expf(Ps[row*1024 + l] - m);
            Ps[row*1024 + l] = e;
            s += e;
        }
        #pragma unroll
        for (int o = 16; o; o >>= 1) s += __shfl_xor_sync(0xffffffffu, s, o);
        if (lane == 0) rinv[row] = 1.f / s;
    }
    __syncthreads();

    // ---- phase 3: out = P @ V ----
    float o0=0.f, o1=0.f, o2=0.f, o3=0.f;
    int dc = jl;
    for (int jc = 0; jc < NTOK; jc += 64) {
        for (int l = t; l < 64*64; l += 256) {
            int j = l >> 6, d = l & 63;
            Ts[j*64 + d] = g_v[(size_t)(jc+j)*INNER + h*DH + d];
        }
        __syncthreads();
        const float* p0 = Ps + (r4*4+0)*1024 + jc;
        const float* p1 = Ps + (r4*4+1)*1024 + jc;
        const float* p2 = Ps + (r4*4+2)*1024 + jc;
        const float* p3 = Ps + (r4*4+3)*1024 + jc;
        #pragma unroll 8
        for (int j = 0; j < 64; j++) {
            float vv = Ts[j*64 + dc];
            o0 += p0[j]*vv; o1 += p1[j]*vv; o2 += p2[j]*vv; o3 += p3[j]*vv;
        }
        __syncthreads();
    }
    g_attnout[(size_t)(i0 + r4*4+0)*INNER + h*DH + dc] = o0 * rinv[r4*4+0];
    g_attnout[(size_t)(i0 + r4*4+1)*INNER + h*DH + dc] = o1 * rinv[r4*4+1];
    g_attnout[(size_t)(i0 + r4*4+2)*INNER + h*DH + dc] = o2 * rinv[r4*4+2];
    g_attnout[(size_t)(i0 + r4*4+3)*INNER + h*DH + dc] = o3 * rinv[r4*4+3];
}

// ---------------- K4: out = (attnout * sigmoid(G)) @ Wo ----------------
__global__ __launch_bounds__(256) void outproj_kernel(
    const float* __restrict__ Wo, float* __restrict__ out)
{
    __shared__ __align__(16) float As[16][64];
    __shared__ __align__(16) float Bs[16][64];
    int t  = threadIdx.x;
    int tx = t & 15, ty = t >> 4;
    int m0 = blockIdx.y * 64;
    int n0 = blockIdx.x * 64;

    float acc[4][4];
    #pragma unroll
    for (int i = 0; i < 4; i++)
        #pragma unroll
        for (int j = 0; j < 4; j++) acc[i][j] = 0.f;

    for (int k0 = 0; k0 < INNER; k0 += 16) {
        {
            int m  = t >> 2;
            int kq = (t & 3) * 4;
            float4 av = *(const float4*)(g_attnout + (size_t)(m0+m)*INNER + k0 + kq);
            float4 gv = *(const float4*)(g_g       + (size_t)(m0+m)*INNER + k0 + kq);
            As[kq+0][m] = av.x * (1.f/(1.f + __expf(-gv.x)));
            As[kq+1][m] = av.y * (1.f/(1.f + __expf(-gv.y)));
            As[kq+2][m] = av.z * (1.f/(1.f + __expf(-gv.z)));
            As[kq+3][m] = av.w * (1.f/(1.f + __expf(-gv.w)));
        }
        {
            int k = t >> 4;
            int n = (t & 15) * 4;
            *(float4*)&Bs[k][n] = *(const float4*)(Wo + (size_t)(k0+k)*DS + n0 + n);
        }
        __syncthreads();
        #pragma unroll
        for (int k = 0; k < 16; k++) {
            float a[4], b[4];
            #pragma unroll
            for (int i = 0; i < 4; i++) a[i] = As[k][ty*4 + i];
            #pragma unroll
            for (int j = 0; j < 4; j++) b[j] = Bs[k][tx*4 + j];
            #pragma unroll
            for (int i = 0; i < 4; i++)
                #pragma unroll
                for (int j = 0; j < 4; j++)
                    acc[i][j] += a[i] * b[j];
        }
        __syncthreads();
    }
    #pragma unroll
    for (int i = 0; i < 4; i++) {
        int m = m0 + ty*4 + i;
        float4 c;
        c.x = acc[i][0]; c.y = acc[i][1]; c.z = acc[i][2]; c.w = acc[i][3];
        *(float4*)(out + (size_t)m*DS + n0 + tx*4) = c;
    }
}

// ---------------- launcher ----------------
extern "C" void kernel_launch(void* const* d_in, const int* in_sizes, int n_in,
                              void* d_out, int out_size)
{
    const float* x     = (const float*)d_in[0];
    const float* pw    = (const float*)d_in[1];
    const float* ab    = (const float*)d_in[2];
    const float* gamma = (const float*)d_in[3];
    const float* beta  = (const float*)d_in[4];
    const float* Wb    = (const float*)d_in[5];
    const float* Wq    = (const float*)d_in[6];
    const float* bq    = (const float*)d_in[7];
    const float* Wk    = (const float*)d_in[8];
    const float* Wv    = (const float*)d_in[9];
    const float* Wg    = (const float*)d_in[10];
    const float* Wo    = (const float*)d_in[11];
    float* out = (float*)d_out;

    prep_kernel<<<1, 256>>>(gamma, beta, Wb);
    proj_kernel<<<dim3(INNER/P_BN, NTOK/P_BM, 4), 256>>>(x, Wq, bq, Wk, Wv, Wg);
    bias_kernel<<<NN/256, 256>>>(pw, ab);

    const int smem_bytes = (16*1024 + 64*65 + 16*64 + 16) * 4;   // 86336
    cudaFuncSetAttribute(attn_kernel, cudaFuncAttributeMaxDynamicSharedMemorySize, smem_bytes);
    attn_kernel<<<dim3(NTOK/16, NH), 256, smem_bytes>>>();

    outproj_kernel<<<dim3(DS/64, NTOK/64), 256>>>(Wo, out);
}

// round 2
// speedup vs baseline: 1.2290x; 1.2290x over previous
#include <cuda_runtime.h>
#include <cstdint>

#define NTOK  1024
#define DS    384
#define DP    128
#define NH    16
#define DH    64
#define INNER 1024
#define NN    (NTOK*NTOK)

// ---------------- scratch (device globals; no allocation allowed) ----------------
__device__ float g_q[NTOK*INNER];
__device__ float g_k[NTOK*INNER];
__device__ float g_v[NTOK*INNER];
__device__ float g_g[NTOK*INNER];
__device__ float g_scores[(size_t)NH*NN];     // 64 MB bias (pre-qk)
__device__ float g_attnout[NTOK*INNER];       // [i][h*64+d]
__device__ float g_gw[NH*DP];
__device__ float g_T[NH];
__device__ float g_U[NH];

__device__ __forceinline__ float to_tf32(float x) {
    float y;
    asm("cvt.rna.tf32.f32 %0, %1;" : "=f"(y) : "f"(x));
    return y;
}
__device__ __forceinline__ void mma_tf32(float c[4],
    uint32_t a0, uint32_t a1, uint32_t a2, uint32_t a3,
    uint32_t b0, uint32_t b1)
{
    asm volatile("mma.sync.aligned.m16n8k8.row.col.f32.tf32.tf32.f32 "
        "{%0,%1,%2,%3}, {%4,%5,%6,%7}, {%8,%9}, {%0,%1,%2,%3};"
        : "+f"(c[0]), "+f"(c[1]), "+f"(c[2]), "+f"(c[3])
        : "r"(a0), "r"(a1), "r"(a2), "r"(a3), "r"(b0), "r"(b1));
}

// ---------------- K0: tiny precompute ----------------
__global__ void prep_kernel(const float* __restrict__ gamma,
                            const float* __restrict__ beta,
                            const float* __restrict__ Wb)
{
    int t = threadIdx.x;
    for (int l = t; l < NH*DP; l += blockDim.x) {
        int h = l / DP, d = l % DP;
        g_gw[h*DP + d] = gamma[d] * Wb[d*NH + h];
    }
    if (t < 2*NH) {
        int h = t % NH;
        const float* src = (t < NH) ? gamma : beta;
        float s = 0.f;
        for (int d = 0; d < DP; d++) s += src[d] * Wb[d*NH + h];
        if (t < NH) g_T[h] = s; else g_U[h] = s;
    }
}

// ---------------- K1: projections ----------------
#define P_BM 128
#define P_BN 64
#define P_BK 16
__global__ __launch_bounds__(256) void proj_kernel(
    const float* __restrict__ X,
    const float* __restrict__ Wq, const float* __restrict__ bq,
    const float* __restrict__ Wk, const float* __restrict__ Wv,
    const float* __restrict__ Wg)
{
    __shared__ __align__(16) float As[P_BK][P_BM];
    __shared__ __align__(16) float Bs[P_BK][P_BN];

    int sel = blockIdx.z;
    const float* W = (sel==0) ? Wq : (sel==1) ? Wk : (sel==2) ? Wv : Wg;
    float* out     = (sel==0) ? g_q : (sel==1) ? g_k : (sel==2) ? g_v : g_g;

    int t  = threadIdx.x;
    int tx = t & 15;
    int ty = t >> 4;
    int m0 = blockIdx.y * P_BM;
    int n0 = blockIdx.x * P_BN;

    float acc[8][4];
    #pragma unroll
    for (int i = 0; i < 8; i++)
        #pragma unroll
        for (int j = 0; j < 4; j++) acc[i][j] = 0.f;

    for (int k0 = 0; k0 < DS; k0 += P_BK) {
        #pragma unroll
        for (int r = 0; r < 2; r++) {
            int s  = t + 256*r;
            int m  = s >> 2;
            int kq = (s & 3) * 4;
            float4 xv = *(const float4*)(X + (m0+m)*DS + k0 + kq);
            As[kq+0][m] = xv.x; As[kq+1][m] = xv.y;
            As[kq+2][m] = xv.z; As[kq+3][m] = xv.w;
        }
        {
            int k = t >> 4;
            int n = (t & 15) * 4;
            *(float4*)&Bs[k][n] = *(const float4*)(W + (k0+k)*INNER + n0 + n);
        }
        __syncthreads();
        #pragma unroll
        for (int k = 0; k < P_BK; k++) {
            float a[8], b[4];
            #pragma unroll
            for (int i = 0; i < 8; i++) a[i] = As[k][ty*8 + i];
            #pragma unroll
            for (int j = 0; j < 4; j++) b[j] = Bs[k][tx*4 + j];
            #pragma unroll
            for (int i = 0; i < 8; i++)
                #pragma unroll
                for (int j = 0; j < 4; j++)
                    acc[i][j] += a[i] * b[j];
        }
        __syncthreads();
    }
    float4 bqv = make_float4(0.f, 0.f, 0.f, 0.f);
    if (sel == 0) bqv = *(const float4*)(bq + n0 + tx*4);
    #pragma unroll
    for (int i = 0; i < 8; i++) {
        int m = m0 + ty*8 + i;
        float4 c;
        c.x = acc[i][0] + bqv.x; c.y = acc[i][1] + bqv.y;
        c.z = acc[i][2] + bqv.z; c.w = acc[i][3] + bqv.w;
        *(float4*)(out + (size_t)m*INNER + n0 + tx*4) = c;
    }
}

// ---------------- K2: fused LN + pw@(gamma*Wb) + attn_bias -> g_scores ----------------
__global__ __launch_bounds__(256) void bias_kernel(
    const float* __restrict__ pw, const float* __restrict__ ab)
{
    __shared__ __align__(16) float gWs[NH][DP];
    __shared__ float Ts[NH], Us[NH];
    int t = threadIdx.x;
    for (int l = t; l < NH*DP; l += 256) ((float*)gWs)[l] = g_gw[l];
    if (t < NH)      Ts[t] = g_T[t];
    else if (t < 2*NH) Us[t-NH] = g_U[t-NH];
    __syncthreads();

    size_t p = (size_t)blockIdx.x * 256 + t;
    const float* x = pw + p * DP;

    float acc[NH];
    #pragma unroll
    for (int h = 0; h < NH; h++) acc[h] = 0.f;
    float sum = 0.f, ssq = 0.f;

    #pragma unroll 4
    for (int d = 0; d < DP; d += 4) {
        float4 xv = *(const float4*)(x + d);
        sum += xv.x + xv.y + xv.z + xv.w;
        ssq += xv.x*xv.x; ssq += xv.y*xv.y; ssq += xv.z*xv.z; ssq += xv.w*xv.w;
        #pragma unroll
        for (int h = 0; h < NH; h++) {
            float4 w = *(const float4*)&gWs[h][d];
            acc[h] += xv.x*w.x + xv.y*w.y + xv.z*w.z + xv.w*w.w;
        }
    }
    float mu   = sum * (1.f/DP);
    float var  = ssq * (1.f/DP) - mu*mu;
    float rinv = rsqrtf(var + 1e-5f);
    float abp  = ab[p];
    #pragma unroll
    for (int h = 0; h < NH; h++) {
        g_scores[(size_t)h*NN + p] = rinv*(acc[h] - mu*Ts[h]) + Us[h] + abp;
    }
}

// ---------------- K3: flash attention, tf32 mma.sync ----------------
// Block: 256 threads = 8 warps (4 along M x 2 along N). Tile: 64 query rows, 1 head.
// Streams 64-key chunks; online softmax; bias streamed from g_scores via smem.
#define SMEM_STRIDE 68
__global__ __launch_bounds__(256) void attn_mma_kernel()
{
    extern __shared__ float sm[];
    float* Qs = sm;                       // 64*68
    float* Kc = Qs + 64*SMEM_STRIDE;      // 64*68
    float* Vc = Kc + 64*SMEM_STRIDE;      // 64*68
    float* Bc = Vc + 64*SMEM_STRIDE;      // 64*68 (bias tile)
    float* Ps = Bc + 64*SMEM_STRIDE;      // 64*68 (P tile; reused as O-combine)
    float* redmax = Ps + 64*SMEM_STRIDE;  // 2*64
    float* redsum = redmax + 128;         // 2*64
    float* m_s = redsum + 128;            // 64
    float* l_s = m_s + 64;                // 64

    const int t   = threadIdx.x;
    const int h   = blockIdx.y;
    const int i0  = blockIdx.x * 64;
    const int wid = t >> 5, lane = t & 31;
    const int wm  = wid >> 1, wn = wid & 1;
    const int g   = lane >> 2, tig = lane & 3;
    const int R0  = wm * 16;
    const int C0  = wn * 32;
    const size_t hbase = (size_t)h * NN;

    // load Q tile (tf32-rounded)
    for (int l = t*4; l < 64*64; l += 1024) {
        int r = l >> 6, d = l & 63;
        float4 v = *(const float4*)(g_q + (size_t)(i0+r)*INNER + h*DH + d);
        float* dst = Qs + r*SMEM_STRIDE + d;
        dst[0] = to_tf32(v.x); dst[1] = to_tf32(v.y);
        dst[2] = to_tf32(v.z); dst[3] = to_tf32(v.w);
    }
    if (t < 64) { m_s[t] = -1e30f; l_s[t] = 0.f; }
    __syncthreads();

    float oc[8][4];
    #pragma unroll
    for (int nt = 0; nt < 8; nt++)
        #pragma unroll
        for (int j = 0; j < 4; j++) oc[nt][j] = 0.f;

    for (int jc = 0; jc < NTOK; jc += 64) {
        // stage K, V (tf32) and bias chunk
        for (int l = t*4; l < 64*64; l += 1024) {
            int r = l >> 6, d = l & 63;
            float4 kv = *(const float4*)(g_k + (size_t)(jc+r)*INNER + h*DH + d);
            float4 vv = *(const float4*)(g_v + (size_t)(jc+r)*INNER + h*DH + d);
            float4 bv = *(const float4*)(g_scores + hbase + (size_t)(i0+r)*NTOK + jc + d);
            float* kd = Kc + r*SMEM_STRIDE + d;
            float* vd = Vc + r*SMEM_STRIDE + d;
            float* bd = Bc + r*SMEM_STRIDE + d;
            kd[0]=to_tf32(kv.x); kd[1]=to_tf32(kv.y); kd[2]=to_tf32(kv.z); kd[3]=to_tf32(kv.w);
            vd[0]=to_tf32(vv.x); vd[1]=to_tf32(vv.y); vd[2]=to_tf32(vv.z); vd[3]=to_tf32(vv.w);
            bd[0]=bv.x; bd[1]=bv.y; bd[2]=bv.z; bd[3]=bv.w;
        }
        __syncthreads();

        // ---- S = Q K^T (64x64, K=64) ----
        float sc[4][4];
        #pragma unroll
        for (int nt = 0; nt < 4; nt++)
            #pragma unroll
            for (int j = 0; j < 4; j++) sc[nt][j] = 0.f;

        #pragma unroll
        for (int kk = 0; kk < 8; kk++) {
            int kb = kk*8;
            uint32_t a0 = __float_as_uint(Qs[(R0+g  )*SMEM_STRIDE + kb+tig]);
            uint32_t a1 = __float_as_uint(Qs[(R0+g+8)*SMEM_STRIDE + kb+tig]);
            uint32_t a2 = __float_as_uint(Qs[(R0+g  )*SMEM_STRIDE + kb+tig+4]);
            uint32_t a3 = __float_as_uint(Qs[(R0+g+8)*SMEM_STRIDE + kb+tig+4]);
            #pragma unroll
            for (int nt = 0; nt < 4; nt++) {
                uint32_t b0 = __float_as_uint(Kc[(C0+nt*8+g)*SMEM_STRIDE + kb+tig]);
                uint32_t b1 = __float_as_uint(Kc[(C0+nt*8+g)*SMEM_STRIDE + kb+tig+4]);
                mma_tf32(sc[nt], a0, a1, a2, a3, b0, b1);
            }
        }

        // ---- scale + bias; chunk row-max ----
        float rm0 = -1e30f, rm1 = -1e30f;
        #pragma unroll
        for (int nt = 0; nt < 4; nt++) {
            int cb = C0 + nt*8 + tig*2;
            sc[nt][0] = sc[nt][0]*0.125f + Bc[(R0+g  )*SMEM_STRIDE + cb];
            sc[nt][1] = sc[nt][1]*0.125f + Bc[(R0+g  )*SMEM_STRIDE + cb+1];
            sc[nt][2] = sc[nt][2]*0.125f + Bc[(R0+g+8)*SMEM_STRIDE + cb];
            sc[nt][3] = sc[nt][3]*0.125f + Bc[(R0+g+8)*SMEM_STRIDE + cb+1];
            rm0 = fmaxf(rm0, fmaxf(sc[nt][0], sc[nt][1]));
            rm1 = fmaxf(rm1, fmaxf(sc[nt][2], sc[nt][3]));
        }
        rm0 = fmaxf(rm0, __shfl_xor_sync(0xffffffffu, rm0, 1));
        rm0 = fmaxf(rm0, __shfl_xor_sync(0xffffffffu, rm0, 2));
        rm1 = fmaxf(rm1, __shfl_xor_sync(0xffffffffu, rm1, 1));
        rm1 = fmaxf(rm1, __shfl_xor_sync(0xffffffffu, rm1, 2));
        if (tig == 0) {
            redmax[wn*64 + R0+g  ] = rm0;
            redmax[wn*64 + R0+g+8] = rm1;
        }
        __syncthreads();

        // ---- online softmax: P = exp(s - m_new), rescale O ----
        float mo0 = m_s[R0+g], mo1 = m_s[R0+g+8];
        float mn0 = fmaxf(mo0, fmaxf(redmax[R0+g  ], redmax[64 + R0+g  ]));
        float mn1 = fmaxf(mo1, fmaxf(redmax[R0+g+8], redmax[64 + R0+g+8]));
        float al0 = __expf(mo0 - mn0);
        float al1 = __expf(mo1 - mn1);
        float ls0 = 0.f, ls1 = 0.f;
        #pragma unroll
        for (int nt = 0; nt < 4; nt++) {
            int cb = C0 + nt*8 + tig*2;
            float p0 = __expf(sc[nt][0] - mn0);
            float p1 = __expf(sc[nt][1] - mn0);
            float p2 = __expf(sc[nt][2] - mn1);
            float p3 = __expf(sc[nt][3] - mn1);
            ls0 += p0 + p1; ls1 += p2 + p3;
            Ps[(R0+g  )*SMEM_STRIDE + cb  ] = to_tf32(p0);
            Ps[(R0+g  )*SMEM_STRIDE + cb+1] = to_tf32(p1);
            Ps[(R0+g+8)*SMEM_STRIDE + cb  ] = to_tf32(p2);
            Ps[(R0+g+8)*SMEM_STRIDE + cb+1] = to_tf32(p3);
        }
        ls0 += __shfl_xor_sync(0xffffffffu, ls0, 1);
        ls0 += __shfl_xor_sync(0xffffffffu, ls0, 2);
        ls1 += __shfl_xor_sync(0xffffffffu, ls1, 1);
        ls1 += __shfl_xor_sync(0xffffffffu, ls1, 2);
        if (tig == 0) {
            redsum[wn*64 + R0+g  ] = ls0;
            redsum[wn*64 + R0+g+8] = ls1;
        }
        #pragma unroll
        for (int nt = 0; nt < 8; nt++) {
            oc[nt][0] *= al0; oc[nt][1] *= al0;
            oc[nt][2] *= al1; oc[nt][3] *= al1;
        }
        __syncthreads();

        if (t < 64) {
            float mo = m_s[t];
            float mn = fmaxf(mo, fmaxf(redmax[t], redmax[64+t]));
            l_s[t] = l_s[t]*__expf(mo - mn) + redsum[t] + redsum[64+t];
            m_s[t] = mn;
        }

        // ---- O += P V  (this warp covers j in [C0, C0+32)) ----
        #pragma unroll
        for (int kk = 0; kk < 4; kk++) {
            int kb = C0 + kk*8;
            uint32_t a0 = __float_as_uint(Ps[(R0+g  )*SMEM_STRIDE + kb+tig]);
            uint32_t a1 = __float_as_uint(Ps[(R0+g+8)*SMEM_STRIDE + kb+tig]);
            uint32_t a2 = __float_as_uint(Ps[(R0+g  )*SMEM_STRIDE + kb+tig+4]);
            uint32_t a3 = __float_as_uint(Ps[(R0+g+8)*SMEM_STRIDE + kb+tig+4]);
            #pragma unroll
            for (int nt = 0; nt < 8; nt++) {
                uint32_t b0 = __float_as_uint(Vc[(kb+tig  )*SMEM_STRIDE + nt*8+g]);
                uint32_t b1 = __float_as_uint(Vc[(kb+tig+4)*SMEM_STRIDE + nt*8+g]);
                mma_tf32(oc[nt], a0, a1, a2, a3, b0, b1);
            }
        }
        __syncthreads();
    }

    // ---- combine the two wn partials, normalize, write out ----
    if (wn == 1) {
        #pragma unroll
        for (int nt = 0; nt < 8; nt++) {
            int cb = nt*8 + tig*2;
            Ps[(R0+g  )*SMEM_STRIDE + cb  ] = oc[nt][0];
            Ps[(R0+g  )*SMEM_STRIDE + cb+1] = oc[nt][1];
            Ps[(R0+g+8)*SMEM_STRIDE + cb  ] = oc[nt][2];
            Ps[(R0+g+8)*SMEM_STRIDE + cb+1] = oc[nt][3];
        }
    }
    __syncthreads();
    if (wn == 0) {
        float inv0 = 1.f / l_s[R0+g];
        float inv1 = 1.f / l_s[R0+g+8];
        #pragma unroll
        for (int nt = 0; nt < 8; nt++) {
            int cb = nt*8 + tig*2;
            float2 v0, v1;
            v0.x = (oc[nt][0] + Ps[(R0+g  )*SMEM_STRIDE + cb  ]) * inv0;
            v0.y = (oc[nt][1] + Ps[(R0+g  )*SMEM_STRIDE + cb+1]) * inv0;
            v1.x = (oc[nt][2] + Ps[(R0+g+8)*SMEM_STRIDE + cb  ]) * inv1;
            v1.y = (oc[nt][3] + Ps[(R0+g+8)*SMEM_STRIDE + cb+1]) * inv1;
            *(float2*)(g_attnout + (size_t)(i0+R0+g  )*INNER + h*DH + cb) = v0;
            *(float2*)(g_attnout + (size_t)(i0+R0+g+8)*INNER + h*DH + cb) = v1;
        }
    }
}

// ---------------- K4: out = (attnout * sigmoid(G)) @ Wo ----------------
__global__ __launch_bounds__(256) void outproj_kernel(
    const float* __restrict__ Wo, float* __restrict__ out)
{
    __shared__ __align__(16) float As[16][64];
    __shared__ __align__(16) float Bs[16][64];
    int t  = threadIdx.x;
    int tx = t & 15, ty = t >> 4;
    int m0 = blockIdx.y * 64;
    int n0 = blockIdx.x * 64;

    float acc[4][4];
    #pragma unroll
    for (int i = 0; i < 4; i++)
        #pragma unroll
        for (int j = 0; j < 4; j++) acc[i][j] = 0.f;

    for (int k0 = 0; k0 < INNER; k0 += 16) {
        {
            int m  = t >> 2;
            int kq = (t & 3) * 4;
            float4 av = *(const float4*)(g_attnout + (size_t)(m0+m)*INNER + k0 + kq);
            float4 gv = *(const float4*)(g_g       + (size_t)(m0+m)*INNER + k0 + kq);
            As[kq+0][m] = av.x * (1.f/(1.f + __expf(-gv.x)));
            As[kq+1][m] = av.y * (1.f/(1.f + __expf(-gv.y)));
            As[kq+2][m] = av.z * (1.f/(1.f + __expf(-gv.z)));
            As[kq+3][m] = av.w * (1.f/(1.f + __expf(-gv.w)));
        }
        {
            int k = t >> 4;
            int n = (t & 15) * 4;
            *(float4*)&Bs[k][n] = *(const float4*)(Wo + (size_t)(k0+k)*DS + n0 + n);
        }
        __syncthreads();
        #pragma unroll
        for (int k = 0; k < 16; k++) {
            float a[4], b[4];
            #pragma unroll
            for (int i = 0; i < 4; i++) a[i] = As[k][ty*4 + i];
            #pragma unroll
            for (int j = 0; j < 4; j++) b[j] = Bs[k][tx*4 + j];
            #pragma unroll
            for (int i = 0; i < 4; i++)
                #pragma unroll
                for (int j = 0; j < 4; j++)
                    acc[i][j] += a[i] * b[j];
        }
        __syncthreads();
    }
    #pragma unroll
    for (int i = 0; i < 4; i++) {
        int m = m0 + ty*4 + i;
        float4 c;
        c.x = acc[i][0]; c.y = acc[i][1]; c.z = acc[i][2]; c.w = acc[i][3];
        *(float4*)(out + (size_t)m*DS + n0 + tx*4) = c;
    }
}

// ---------------- launcher ----------------
extern "C" void kernel_launch(void* const* d_in, const int* in_sizes, int n_in,
                              void* d_out, int out_size)
{
    const float* x     = (const float*)d_in[0];
    const float* pw    = (const float*)d_in[1];
    const float* ab    = (const float*)d_in[2];
    const float* gamma = (const float*)d_in[3];
    const float* beta  = (const float*)d_in[4];
    const float* Wb    = (const float*)d_in[5];
    const float* Wq    = (const float*)d_in[6];
    const float* bq    = (const float*)d_in[7];
    const float* Wk    = (const float*)d_in[8];
    const float* Wv    = (const float*)d_in[9];
    const float* Wg    = (const float*)d_in[10];
    const float* Wo    = (const float*)d_in[11];
    float* out = (float*)d_out;

    prep_kernel<<<1, 256>>>(gamma, beta, Wb);
    proj_kernel<<<dim3(INNER/P_BN, NTOK/P_BM, 4), 256>>>(x, Wq, bq, Wk, Wv, Wg);
    bias_kernel<<<NN/256, 256>>>(pw, ab);

    const int smem_bytes = (5*64*SMEM_STRIDE + 2*64 + 2*64 + 64 + 64) * 4;
    cudaFuncSetAttribute(attn_mma_kernel, cudaFuncAttributeMaxDynamicSharedMemorySize, smem_bytes);
    attn_mma_kernel<<<dim3(NTOK/64, NH), 256, smem_bytes>>>();

    outproj_kernel<<<dim3(DS/64, NTOK/64), 256>>>(Wo, out);
}

// round 4
// speedup vs baseline: 2.2750x; 1.8511x over previous
#include <cuda_runtime.h>
#include <cstdint>

#define NTOK  1024
#define DS    384
#define DP    128
#define NH    16
#define DH    64
#define INNER 1024
#define NN    (NTOK*NTOK)

// ---------------- scratch ----------------
__device__ float g_q[NTOK*INNER];
__device__ float g_k[NTOK*INNER];
__device__ float g_v[NTOK*INNER];
__device__ float g_g[NTOK*INNER];
__device__ float g_scores[(size_t)NH*NN];
__device__ float g_attnout[NTOK*INNER];
__device__ float g_gw[NH*DP];
__device__ float g_T[NH];
__device__ float g_U[NH];

__device__ __forceinline__ float to_tf32(float x) {
    float y;
    asm("cvt.rna.tf32.f32 %0, %1;" : "=f"(y) : "f"(x));
    return y;
}
__device__ __forceinline__ void mma_tf32(float c[4],
    uint32_t a0, uint32_t a1, uint32_t a2, uint32_t a3,
    uint32_t b0, uint32_t b1)
{
    asm volatile("mma.sync.aligned.m16n8k8.row.col.f32.tf32.tf32.f32 "
        "{%0,%1,%2,%3}, {%4,%5,%6,%7}, {%8,%9}, {%0,%1,%2,%3};"
        : "+f"(c[0]), "+f"(c[1]), "+f"(c[2]), "+f"(c[3])
        : "r"(a0), "r"(a1), "r"(a2), "r"(a3), "r"(b0), "r"(b1));
}

// ---------------- K0: tiny precompute ----------------
__global__ void prep_kernel(const float* __restrict__ gamma,
                            const float* __restrict__ beta,
                            const float* __restrict__ Wb)
{
    int t = threadIdx.x;
    for (int l = t; l < NH*DP; l += blockDim.x) {
        int h = l / DP, d = l % DP;
        g_gw[h*DP + d] = gamma[d] * Wb[d*NH + h];
    }
    if (t < 2*NH) {
        int h = t % NH;
        const float* src = (t < NH) ? gamma : beta;
        float s = 0.f;
        for (int d = 0; d < DP; d++) s += src[d] * Wb[d*NH + h];
        if (t < NH) g_T[h] = s; else g_U[h] = s;
    }
}

// ---------------- generic tf32 mma GEMM: C[M,ldc] = op(A[M,KD]) @ B[KD,ldb] ----------------
// BM=64, BN=64, BK=16. 8 warps as 2(m) x 4(n); warp tile 32x16.
#define AS_S 20
#define BS_S 72
template<int KD, bool GATE>
__global__ __launch_bounds__(256) void gemm_tf32(
    const float* __restrict__ A, const float* __restrict__ Gt,
    const float* __restrict__ B, const float* __restrict__ bias,
    float* __restrict__ C, int ldb, int ldc)
{
    __shared__ __align__(16) float As[64*AS_S];
    __shared__ __align__(16) float Bs[16*BS_S];

    const int t = threadIdx.x;
    const int m0 = blockIdx.y * 64;
    const int n0 = blockIdx.x * 64;
    const int wid = t >> 5, lane = t & 31;
    const int wm = wid & 1, wn = wid >> 1;
    const int g = lane >> 2, tig = lane & 3;
    const int R0 = wm * 32, C0 = wn * 16;

    float c[2][2][4];
    #pragma unroll
    for (int mt = 0; mt < 2; mt++)
        #pragma unroll
        for (int nt = 0; nt < 2; nt++)
            #pragma unroll
            for (int j = 0; j < 4; j++) c[mt][nt][j] = 0.f;

    const int am = t >> 2, akq = (t & 3) * 4;
    const int bk = t >> 4, bn4 = (t & 15) * 4;

    for (int k0 = 0; k0 < KD; k0 += 16) {
        {
            float4 av = *(const float4*)(A + (size_t)(m0+am)*KD + k0 + akq);
            if (GATE) {
                float4 gv = *(const float4*)(Gt + (size_t)(m0+am)*KD + k0 + akq);
                av.x *= 1.f/(1.f + __expf(-gv.x));
                av.y *= 1.f/(1.f + __expf(-gv.y));
                av.z *= 1.f/(1.f + __expf(-gv.z));
                av.w *= 1.f/(1.f + __expf(-gv.w));
            }
            float* d = As + am*AS_S + akq;
            d[0]=to_tf32(av.x); d[1]=to_tf32(av.y); d[2]=to_tf32(av.z); d[3]=to_tf32(av.w);
        }
        {
            float4 bv = *(const float4*)(B + (size_t)(k0+bk)*ldb + n0 + bn4);
            float* d = Bs + bk*BS_S + bn4;
            d[0]=to_tf32(bv.x); d[1]=to_tf32(bv.y); d[2]=to_tf32(bv.z); d[3]=to_tf32(bv.w);
        }
        __syncthreads();
        #pragma unroll
        for (int kk = 0; kk < 2; kk++) {
            int kb = kk * 8;
            uint32_t b0[2], b1[2];
            #pragma unroll
            for (int nt = 0; nt < 2; nt++) {
                b0[nt] = __float_as_uint(Bs[(kb+tig  )*BS_S + C0 + nt*8 + g]);
                b1[nt] = __float_as_uint(Bs[(kb+tig+4)*BS_S + C0 + nt*8 + g]);
            }
            #pragma unroll
            for (int mt = 0; mt < 2; mt++) {
                uint32_t a0 = __float_as_uint(As[(R0+mt*16+g  )*AS_S + kb+tig]);
                uint32_t a1 = __float_as_uint(As[(R0+mt*16+g+8)*AS_S + kb+tig]);
                uint32_t a2 = __float_as_uint(As[(R0+mt*16+g  )*AS_S + kb+tig+4]);
                uint32_t a3 = __float_as_uint(As[(R0+mt*16+g+8)*AS_S + kb+tig+4]);
                #pragma unroll
                for (int nt = 0; nt < 2; nt++)
                    mma_tf32(c[mt][nt], a0, a1, a2, a3, b0[nt], b1[nt]);
            }
        }
        __syncthreads();
    }

    #pragma unroll
    for (int mt = 0; mt < 2; mt++) {
        #pragma unroll
        for (int nt = 0; nt < 2; nt++) {
            int n = n0 + C0 + nt*8 + tig*2;
            float bx = 0.f, by = 0.f;
            if (bias) { bx = bias[n]; by = bias[n+1]; }
            int r0 = m0 + R0 + mt*16 + g;
            float2 v0 = make_float2(c[mt][nt][0] + bx, c[mt][nt][1] + by);
            float2 v1 = make_float2(c[mt][nt][2] + bx, c[mt][nt][3] + by);
            *(float2*)(C + (size_t)r0*ldc + n)     = v0;
            *(float2*)(C + (size_t)(r0+8)*ldc + n) = v1;
        }
    }
}

// ---------------- K2: bias via mma — LN folded, moments fused with fragment loads ----------------
#define BW_S 24
__global__ __launch_bounds__(256) void bias_mma_kernel(
    const float* __restrict__ pw, const float* __restrict__ ab)
{
    __shared__ float Ws[128*BW_S];   // gw transposed [d][h], tf32
    __shared__ float Ss[128*17];     // scores transpose buffer
    __shared__ float Ts[16], Us[16];

    int t = threadIdx.x;
    for (int l = t; l < 16*128; l += 256) {
        int h = l >> 7, d = l & 127;
        Ws[d*BW_S + h] = to_tf32(g_gw[h*DP + d]);
    }
    if (t < 16) Ts[t] = g_T[t];
    else if (t < 32) Us[t-16] = g_U[t-16];
    __syncthreads();

    const int wid = t >> 5, lane = t & 31;
    const int g = lane >> 2, tig = lane & 3;
    const size_t p0 = (size_t)blockIdx.x*128 + wid*16;
    const float* xr0 = pw + (p0 + g    ) * DP;
    const float* xr1 = pw + (p0 + g + 8) * DP;

    float c[2][4];
    #pragma unroll
    for (int nt = 0; nt < 2; nt++)
        #pragma unroll
        for (int j = 0; j < 4; j++) c[nt][j] = 0.f;
    float s0 = 0.f, q0 = 0.f, s1 = 0.f, q1 = 0.f;

    #pragma unroll
    for (int ks = 0; ks < 16; ks++) {
        int kb = ks * 8;
        float a0 = __ldg(xr0 + kb + tig);
        float a1 = __ldg(xr1 + kb + tig);
        float a2 = __ldg(xr0 + kb + tig + 4);
        float a3 = __ldg(xr1 + kb + tig + 4);
        s0 += a0 + a2;  q0 += a0*a0 + a2*a2;
        s1 += a1 + a3;  q1 += a1*a1 + a3*a3;
        uint32_t u0 = __float_as_uint(to_tf32(a0));
        uint32_t u1 = __float_as_uint(to_tf32(a1));
        uint32_t u2 = __float_as_uint(to_tf32(a2));
        uint32_t u3 = __float_as_uint(to_tf32(a3));
        #pragma unroll
        for (int nt = 0; nt < 2; nt++) {
            uint32_t b0 = __float_as_uint(Ws[(kb+tig  )*BW_S + nt*8 + g]);
            uint32_t b1 = __float_as_uint(Ws[(kb+tig+4)*BW_S + nt*8 + g]);
            mma_tf32(c[nt], u0, u1, u2, u3, b0, b1);
        }
    }
    s0 += __shfl_xor_sync(0xffffffffu, s0, 1); s0 += __shfl_xor_sync(0xffffffffu, s0, 2);
    q0 += __shfl_xor_sync(0xffffffffu, q0, 1); q0 += __shfl_xor_sync(0xffffffffu, q0, 2);
    s1 += __shfl_xor_sync(0xffffffffu, s1, 1); s1 += __shfl_xor_sync(0xffffffffu, s1, 2);
    q1 += __shfl_xor_sync(0xffffffffu, q1, 1); q1 += __shfl_xor_sync(0xffffffffu, q1, 2);

    float mu0 = s0 * (1.f/DP), mu1 = s1 * (1.f/DP);
    float rinv0 = rsqrtf(q0*(1.f/DP) - mu0*mu0 + 1e-5f);
    float rinv1 = rsqrtf(q1*(1.f/DP) - mu1*mu1 + 1e-5f);
    float ab0 = ab[p0 + g], ab1 = ab[p0 + g + 8];

    int r0 = wid*16 + g;
    #pragma unroll
    for (int nt = 0; nt < 2; nt++) {
        #pragma unroll
        for (int j = 0; j < 2; j++) {
            int h = nt*8 + tig*2 + j;
            float Th = Ts[h], Uh = Us[h];
            Ss[(r0    )*17 + h] = rinv0*(c[nt][j  ] - mu0*Th) + Uh + ab0;
            Ss[(r0 + 8)*17 + h] = rinv1*(c[nt][2+j] - mu1*Th) + Uh + ab1;
        }
    }
    __syncthreads();
    size_t pb = (size_t)blockIdx.x * 128;
    for (int l = t; l < 2048; l += 256) {
        int h = l >> 7, r = l & 127;
        g_scores[(size_t)h*NN + pb + r] = Ss[r*17 + h];
    }
}

// ---------------- K3: flash attention, tf32 mma (unchanged from R2) ----------------
#define SMEM_STRIDE 68
__global__ __launch_bounds__(256) void attn_mma_kernel()
{
    extern __shared__ float sm[];
    float* Qs = sm;
    float* Kc = Qs + 64*SMEM_STRIDE;
    float* Vc = Kc + 64*SMEM_STRIDE;
    float* Bc = Vc + 64*SMEM_STRIDE;
    float* Ps = Bc + 64*SMEM_STRIDE;
    float* redmax = Ps + 64*SMEM_STRIDE;
    float* redsum = redmax + 128;
    float* m_s = redsum + 128;
    float* l_s = m_s + 64;

    const int t   = threadIdx.x;
    const int h   = blockIdx.y;
    const int i0  = blockIdx.x * 64;
    const int wid = t >> 5, lane = t & 31;
    const int wm  = wid >> 1, wn = wid & 1;
    const int g   = lane >> 2, tig = lane & 3;
    const int R0  = wm * 16;
    const int C0  = wn * 32;
    const size_t hbase = (size_t)h * NN;

    for (int l = t*4; l < 64*64; l += 1024) {
        int r = l >> 6, d = l & 63;
        float4 v = *(const float4*)(g_q + (size_t)(i0+r)*INNER + h*DH + d);
        float* dst = Qs + r*SMEM_STRIDE + d;
        dst[0] = to_tf32(v.x); dst[1] = to_tf32(v.y);
        dst[2] = to_tf32(v.z); dst[3] = to_tf32(v.w);
    }
    if (t < 64) { m_s[t] = -1e30f; l_s[t] = 0.f; }
    __syncthreads();

    float oc[8][4];
    #pragma unroll
    for (int nt = 0; nt < 8; nt++)
        #pragma unroll
        for (int j = 0; j < 4; j++) oc[nt][j] = 0.f;

    for (int jc = 0; jc < NTOK; jc += 64) {
        for (int l = t*4; l < 64*64; l += 1024) {
            int r = l >> 6, d = l & 63;
            float4 kv = *(const float4*)(g_k + (size_t)(jc+r)*INNER + h*DH + d);
            float4 vv = *(const float4*)(g_v + (size_t)(jc+r)*INNER + h*DH + d);
            float4 bv = *(const float4*)(g_scores + hbase + (size_t)(i0+r)*NTOK + jc + d);
            float* kd = Kc + r*SMEM_STRIDE + d;
            float* vd = Vc + r*SMEM_STRIDE + d;
            float* bd = Bc + r*SMEM_STRIDE + d;
            kd[0]=to_tf32(kv.x); kd[1]=to_tf32(kv.y); kd[2]=to_tf32(kv.z); kd[3]=to_tf32(kv.w);
            vd[0]=to_tf32(vv.x); vd[1]=to_tf32(vv.y); vd[2]=to_tf32(vv.z); vd[3]=to_tf32(vv.w);
            bd[0]=bv.x; bd[1]=bv.y; bd[2]=bv.z; bd[3]=bv.w;
        }
        __syncthreads();

        float sc[4][4];
        #pragma unroll
        for (int nt = 0; nt < 4; nt++)
            #pragma unroll
            for (int j = 0; j < 4; j++) sc[nt][j] = 0.f;

        #pragma unroll
        for (int kk = 0; kk < 8; kk++) {
            int kb = kk*8;
            uint32_t a0 = __float_as_uint(Qs[(R0+g  )*SMEM_STRIDE + kb+tig]);
            uint32_t a1 = __float_as_uint(Qs[(R0+g+8)*SMEM_STRIDE + kb+tig]);
            uint32_t a2 = __float_as_uint(Qs[(R0+g  )*SMEM_STRIDE + kb+tig+4]);
            uint32_t a3 = __float_as_uint(Qs[(R0+g+8)*SMEM_STRIDE + kb+tig+4]);
            #pragma unroll
            for (int nt = 0; nt < 4; nt++) {
                uint32_t b0 = __float_as_uint(Kc[(C0+nt*8+g)*SMEM_STRIDE + kb+tig]);
                uint32_t b1 = __float_as_uint(Kc[(C0+nt*8+g)*SMEM_STRIDE + kb+tig+4]);
                mma_tf32(sc[nt], a0, a1, a2, a3, b0, b1);
            }
        }

        float rm0 = -1e30f, rm1 = -1e30f;
        #pragma unroll
        for (int nt = 0; nt < 4; nt++) {
            int cb = C0 + nt*8 + tig*2;
            sc[nt][0] = sc[nt][0]*0.125f + Bc[(R0+g  )*SMEM_STRIDE + cb];
            sc[nt][1] = sc[nt][1]*0.125f + Bc[(R0+g  )*SMEM_STRIDE + cb+1];
            sc[nt][2] = sc[nt][2]*0.125f + Bc[(R0+g+8)*SMEM_STRIDE + cb];
            sc[nt][3] = sc[nt][3]*0.125f + Bc[(R0+g+8)*SMEM_STRIDE + cb+1];
            rm0 = fmaxf(rm0, fmaxf(sc[nt][0], sc[nt][1]));
            rm1 = fmaxf(rm1, fmaxf(sc[nt][2], sc[nt][3]));
        }
        rm0 = fmaxf(rm0, __shfl_xor_sync(0xffffffffu, rm0, 1));
        rm0 = fmaxf(rm0, __shfl_xor_sync(0xffffffffu, rm0, 2));
        rm1 = fmaxf(rm1, __shfl_xor_sync(0xffffffffu, rm1, 1));
        rm1 = fmaxf(rm1, __shfl_xor_sync(0xffffffffu, rm1, 2));
        if (tig == 0) {
            redmax[wn*64 + R0+g  ] = rm0;
            redmax[wn*64 + R0+g+8] = rm1;
        }
        __syncthreads();

        float mo0 = m_s[R0+g], mo1 = m_s[R0+g+8];
        float mn0 = fmaxf(mo0, fmaxf(redmax[R0+g  ], redmax[64 + R0+g  ]));
        float mn1 = fmaxf(mo1, fmaxf(redmax[R0+g+8], redmax[64 + R0+g+8]));
        float al0 = __expf(mo0 - mn0);
        float al1 = __expf(mo1 - mn1);
        float ls0 = 0.f, ls1 = 0.f;
        #pragma unroll
        for (int nt = 0; nt < 4; nt++) {
            int cb = C0 + nt*8 + tig*2;
            float p0 = __expf(sc[nt][0] - mn0);
            float p1 = __expf(sc[nt][1] - mn0);
            float p2 = __expf(sc[nt][2] - mn1);
            float p3 = __expf(sc[nt][3] - mn1);
            ls0 += p0 + p1; ls1 += p2 + p3;
            Ps[(R0+g  )*SMEM_STRIDE + cb  ] = to_tf32(p0);
            Ps[(R0+g  )*SMEM_STRIDE + cb+1] = to_tf32(p1);
            Ps[(R0+g+8)*SMEM_STRIDE + cb  ] = to_tf32(p2);
            Ps[(R0+g+8)*SMEM_STRIDE + cb+1] = to_tf32(p3);
        }
        ls0 += __shfl_xor_sync(0xffffffffu, ls0, 1);
        ls0 += __shfl_xor_sync(0xffffffffu, ls0, 2);
        ls1 += __shfl_xor_sync(0xffffffffu, ls1, 1);
        ls1 += __shfl_xor_sync(0xffffffffu, ls1, 2);
        if (tig == 0) {
            redsum[wn*64 + R0+g  ] = ls0;
            redsum[wn*64 + R0+g+8] = ls1;
        }
        #pragma unroll
        for (int nt = 0; nt < 8; nt++) {
            oc[nt][0] *= al0; oc[nt][1] *= al0;
            oc[nt][2] *= al1; oc[nt][3] *= al1;
        }
        __syncthreads();

        if (t < 64) {
            float mo = m_s[t];
            float mn = fmaxf(mo, fmaxf(redmax[t], redmax[64+t]));
            l_s[t] = l_s[t]*__expf(mo - mn) + redsum[t] + redsum[64+t];
            m_s[t] = mn;
        }

        #pragma unroll
        for (int kk = 0; kk < 4; kk++) {
            int kb = C0 + kk*8;
            uint32_t a0 = __float_as_uint(Ps[(R0+g  )*SMEM_STRIDE + kb+tig]);
            uint32_t a1 = __float_as_uint(Ps[(R0+g+8)*SMEM_STRIDE + kb+tig]);
            uint32_t a2 = __float_as_uint(Ps[(R0+g  )*SMEM_STRIDE + kb+tig+4]);
            uint32_t a3 = __float_as_uint(Ps[(R0+g+8)*SMEM_STRIDE + kb+tig+4]);
            #pragma unroll
            for (int nt = 0; nt < 8; nt++) {
                uint32_t b0 = __float_as_uint(Vc[(kb+tig  )*SMEM_STRIDE + nt*8+g]);
                uint32_t b1 = __float_as_uint(Vc[(kb+tig+4)*SMEM_STRIDE + nt*8+g]);
                mma_tf32(oc[nt], a0, a1, a2, a3, b0, b1);
            }
        }
        __syncthreads();
    }

    if (wn == 1) {
        #pragma unroll
        for (int nt = 0; nt < 8; nt++) {
            int cb = nt*8 + tig*2;
            Ps[(R0+g  )*SMEM_STRIDE + cb  ] = oc[nt][0];
            Ps[(R0+g  )*SMEM_STRIDE + cb+1] = oc[nt][1];
            Ps[(R0+g+8)*SMEM_STRIDE + cb  ] = oc[nt][2];
            Ps[(R0+g+8)*SMEM_STRIDE + cb+1] = oc[nt][3];
        }
    }
    __syncthreads();
    if (wn == 0) {
        float inv0 = 1.f / l_s[R0+g];
        float inv1 = 1.f / l_s[R0+g+8];
        #pragma unroll
        for (int nt = 0; nt < 8; nt++) {
            int cb = nt*8 + tig*2;
            float2 v0, v1;
            v0.x = (oc[nt][0] + Ps[(R0+g  )*SMEM_STRIDE + cb  ]) * inv0;
            v0.y = (oc[nt][1] + Ps[(R0+g  )*SMEM_STRIDE + cb+1]) * inv0;
            v1.x = (oc[nt][2] + Ps[(R0+g+8)*SMEM_STRIDE + cb  ]) * inv1;
            v1.y = (oc[nt][3] + Ps[(R0+g+8)*SMEM_STRIDE + cb+1]) * inv1;
            *(float2*)(g_attnout + (size_t)(i0+R0+g  )*INNER + h*DH + cb) = v0;
            *(float2*)(g_attnout + (size_t)(i0+R0+g+8)*INNER + h*DH + cb) = v1;
        }
    }
}

// ---------------- launcher ----------------
extern "C" void kernel_launch(void* const* d_in, const int* in_sizes, int n_in,
                              void* d_out, int out_size)
{
    const float* x     = (const float*)d_in[0];
    const float* pw    = (const float*)d_in[1];
    const float* ab    = (const float*)d_in[2];
    const float* gamma = (const float*)d_in[3];
    const float* beta  = (const float*)d_in[4];
    const float* Wb    = (const float*)d_in[5];
    const float* Wq    = (const float*)d_in[6];
    const float* bq    = (const float*)d_in[7];
    const float* Wk    = (const float*)d_in[8];
    const float* Wv    = (const float*)d_in[9];
    const float* Wg    = (const float*)d_in[10];
    const float* Wo    = (const float*)d_in[11];
    float* out = (float*)d_out;

    float* dq; cudaGetSymbolAddress((void**)&dq, g_q);
    float* dk; cudaGetSymbolAddress((void**)&dk, g_k);
    float* dv; cudaGetSymbolAddress((void**)&dv, g_v);
    float* dg; cudaGetSymbolAddress((void**)&dg, g_g);
    float* dao; cudaGetSymbolAddress((void**)&dao, g_attnout);

    prep_kernel<<<1, 256>>>(gamma, beta, Wb);

    dim3 pgrid(INNER/64, NTOK/64);
    gemm_tf32<DS, false><<<pgrid, 256>>>(x, nullptr, Wq, bq,      dq, INNER, INNER);
    gemm_tf32<DS, false><<<pgrid, 256>>>(x, nullptr, Wk, nullptr, dk, INNER, INNER);
    gemm_tf32<DS, false><<<pgrid, 256>>>(x, nullptr, Wv, nullptr, dv, INNER, INNER);
    gemm_tf32<DS, false><<<pgrid, 256>>>(x, nullptr, Wg, nullptr, dg, INNER, INNER);

    bias_mma_kernel<<<NN/128, 256>>>(pw, ab);

    const int smem_bytes = (5*64*SMEM_STRIDE + 2*64 + 2*64 + 64 + 64) * 4;
    cudaFuncSetAttribute(attn_mma_kernel, cudaFuncAttributeMaxDynamicSharedMemorySize, smem_bytes);
    attn_mma_kernel<<<dim3(NTOK/64, NH), 256, smem_bytes>>>();

    gemm_tf32<INNER, true><<<dim3(DS/64, NTOK/64), 256>>>(dao, dg, Wo, nullptr, out, DS, DS);
}

// round 5
// speedup vs baseline: 2.7796x; 1.2218x over previous
#include <cuda_runtime.h>
#include <cstdint>

#define NTOK  1024
#define DS    384
#define DP    128
#define NH    16
#define DH    64
#define INNER 1024
#define NN    (NTOK*NTOK)

// ---------------- scratch ----------------
__device__ float g_q[NTOK*INNER];
__device__ float g_k[NTOK*INNER];
__device__ float g_v[NTOK*INNER];
__device__ float g_g[NTOK*INNER];
__device__ float g_scores[(size_t)NH*NN];
__device__ float g_attnout[NTOK*INNER];
__device__ float g_gw[NH*DP];
__device__ float g_T[NH];
__device__ float g_U[NH];

__device__ __forceinline__ float to_tf32(float x) {
    float y;
    asm("cvt.rna.tf32.f32 %0, %1;" : "=f"(y) : "f"(x));
    return y;
}
__device__ __forceinline__ void mma_tf32(float c[4],
    uint32_t a0, uint32_t a1, uint32_t a2, uint32_t a3,
    uint32_t b0, uint32_t b1)
{
    asm volatile("mma.sync.aligned.m16n8k8.row.col.f32.tf32.tf32.f32 "
        "{%0,%1,%2,%3}, {%4,%5,%6,%7}, {%8,%9}, {%0,%1,%2,%3};"
        : "+f"(c[0]), "+f"(c[1]), "+f"(c[2]), "+f"(c[3])
        : "r"(a0), "r"(a1), "r"(a2), "r"(a3), "r"(b0), "r"(b1));
}

// ---------------- K0: tiny precompute ----------------
__global__ void prep_kernel(const float* __restrict__ gamma,
                            const float* __restrict__ beta,
                            const float* __restrict__ Wb)
{
    int t = threadIdx.x;
    for (int l = t; l < NH*DP; l += blockDim.x) {
        int h = l / DP, d = l % DP;
        g_gw[h*DP + d] = gamma[d] * Wb[d*NH + h];
    }
    if (t < 2*NH) {
        int h = t % NH;
        const float* src = (t < NH) ? gamma : beta;
        float s = 0.f;
        for (int d = 0; d < DP; d++) s += src[d] * Wb[d*NH + h];
        if (t < NH) g_T[h] = s; else g_U[h] = s;
    }
}

// ---------------- K1: 4 projections in one launch (z = which W) ----------------
#define AS_S 20
#define BS_S 72
__global__ __launch_bounds__(256) void proj4_kernel(
    const float* __restrict__ X,
    const float* __restrict__ Wq, const float* __restrict__ bq,
    const float* __restrict__ Wk, const float* __restrict__ Wv,
    const float* __restrict__ Wg)
{
    __shared__ __align__(16) float As[64*AS_S];
    __shared__ __align__(16) float Bs[16*BS_S];

    const int sel = blockIdx.z;
    const float* B = (sel==0) ? Wq : (sel==1) ? Wk : (sel==2) ? Wv : Wg;
    float* C       = (sel==0) ? g_q : (sel==1) ? g_k : (sel==2) ? g_v : g_g;

    const int t = threadIdx.x;
    const int m0 = blockIdx.y * 64;
    const int n0 = blockIdx.x * 64;
    const int wid = t >> 5, lane = t & 31;
    const int wm = wid & 1, wn = wid >> 1;
    const int g = lane >> 2, tig = lane & 3;
    const int R0 = wm * 32, C0 = wn * 16;

    float c[2][2][4];
    #pragma unroll
    for (int mt = 0; mt < 2; mt++)
        #pragma unroll
        for (int nt = 0; nt < 2; nt++)
            #pragma unroll
            for (int j = 0; j < 4; j++) c[mt][nt][j] = 0.f;

    const int am = t >> 2, akq = (t & 3) * 4;
    const int bk = t >> 4, bn4 = (t & 15) * 4;

    for (int k0 = 0; k0 < DS; k0 += 16) {
        {
            float4 av = *(const float4*)(X + (size_t)(m0+am)*DS + k0 + akq);
            float* d = As + am*AS_S + akq;
            d[0]=to_tf32(av.x); d[1]=to_tf32(av.y); d[2]=to_tf32(av.z); d[3]=to_tf32(av.w);
        }
        {
            float4 bv = *(const float4*)(B + (size_t)(k0+bk)*INNER + n0 + bn4);
            float* d = Bs + bk*BS_S + bn4;
            d[0]=to_tf32(bv.x); d[1]=to_tf32(bv.y); d[2]=to_tf32(bv.z); d[3]=to_tf32(bv.w);
        }
        __syncthreads();
        #pragma unroll
        for (int kk = 0; kk < 2; kk++) {
            int kb = kk * 8;
            uint32_t b0[2], b1[2];
            #pragma unroll
            for (int nt = 0; nt < 2; nt++) {
                b0[nt] = __float_as_uint(Bs[(kb+tig  )*BS_S + C0 + nt*8 + g]);
                b1[nt] = __float_as_uint(Bs[(kb+tig+4)*BS_S + C0 + nt*8 + g]);
            }
            #pragma unroll
            for (int mt = 0; mt < 2; mt++) {
                uint32_t a0 = __float_as_uint(As[(R0+mt*16+g  )*AS_S + kb+tig]);
                uint32_t a1 = __float_as_uint(As[(R0+mt*16+g+8)*AS_S + kb+tig]);
                uint32_t a2 = __float_as_uint(As[(R0+mt*16+g  )*AS_S + kb+tig+4]);
                uint32_t a3 = __float_as_uint(As[(R0+mt*16+g+8)*AS_S + kb+tig+4]);
                #pragma unroll
                for (int nt = 0; nt < 2; nt++)
                    mma_tf32(c[mt][nt], a0, a1, a2, a3, b0[nt], b1[nt]);
            }
        }
        __syncthreads();
    }

    #pragma unroll
    for (int mt = 0; mt < 2; mt++) {
        #pragma unroll
        for (int nt = 0; nt < 2; nt++) {
            int n = n0 + C0 + nt*8 + tig*2;
            float bx = 0.f, by = 0.f;
            if (sel == 0) { bx = bq[n]; by = bq[n+1]; }
            int r0 = m0 + R0 + mt*16 + g;
            *(float2*)(C + (size_t)r0*INNER + n)     = make_float2(c[mt][nt][0]+bx, c[mt][nt][1]+by);
            *(float2*)(C + (size_t)(r0+8)*INNER + n) = make_float2(c[mt][nt][2]+bx, c[mt][nt][3]+by);
        }
    }
}

// ---------------- generic tf32 mma GEMM (used for outproj) ----------------
template<int KD, bool GATE>
__global__ __launch_bounds__(256) void gemm_tf32(
    const float* __restrict__ A, const float* __restrict__ Gt,
    const float* __restrict__ B, const float* __restrict__ bias,
    float* __restrict__ C, int ldb, int ldc)
{
    __shared__ __align__(16) float As[64*AS_S];
    __shared__ __align__(16) float Bs[16*BS_S];

    const int t = threadIdx.x;
    const int m0 = blockIdx.y * 64;
    const int n0 = blockIdx.x * 64;
    const int wid = t >> 5, lane = t & 31;
    const int wm = wid & 1, wn = wid >> 1;
    const int g = lane >> 2, tig = lane & 3;
    const int R0 = wm * 32, C0 = wn * 16;

    float c[2][2][4];
    #pragma unroll
    for (int mt = 0; mt < 2; mt++)
        #pragma unroll
        for (int nt = 0; nt < 2; nt++)
            #pragma unroll
            for (int j = 0; j < 4; j++) c[mt][nt][j] = 0.f;

    const int am = t >> 2, akq = (t & 3) * 4;
    const int bk = t >> 4, bn4 = (t & 15) * 4;

    for (int k0 = 0; k0 < KD; k0 += 16) {
        {
            float4 av = *(const float4*)(A + (size_t)(m0+am)*KD + k0 + akq);
            if (GATE) {
                float4 gv = *(const float4*)(Gt + (size_t)(m0+am)*KD + k0 + akq);
                av.x *= 1.f/(1.f + __expf(-gv.x));
                av.y *= 1.f/(1.f + __expf(-gv.y));
                av.z *= 1.f/(1.f + __expf(-gv.z));
                av.w *= 1.f/(1.f + __expf(-gv.w));
            }
            float* d = As + am*AS_S + akq;
            d[0]=to_tf32(av.x); d[1]=to_tf32(av.y); d[2]=to_tf32(av.z); d[3]=to_tf32(av.w);
        }
        {
            float4 bv = *(const float4*)(B + (size_t)(k0+bk)*ldb + n0 + bn4);
            float* d = Bs + bk*BS_S + bn4;
            d[0]=to_tf32(bv.x); d[1]=to_tf32(bv.y); d[2]=to_tf32(bv.z); d[3]=to_tf32(bv.w);
        }
        __syncthreads();
        #pragma unroll
        for (int kk = 0; kk < 2; kk++) {
            int kb = kk * 8;
            uint32_t b0[2], b1[2];
            #pragma unroll
            for (int nt = 0; nt < 2; nt++) {
                b0[nt] = __float_as_uint(Bs[(kb+tig  )*BS_S + C0 + nt*8 + g]);
                b1[nt] = __float_as_uint(Bs[(kb+tig+4)*BS_S + C0 + nt*8 + g]);
            }
            #pragma unroll
            for (int mt = 0; mt < 2; mt++) {
                uint32_t a0 = __float_as_uint(As[(R0+mt*16+g  )*AS_S + kb+tig]);
                uint32_t a1 = __float_as_uint(As[(R0+mt*16+g+8)*AS_S + kb+tig]);
                uint32_t a2 = __float_as_uint(As[(R0+mt*16+g  )*AS_S + kb+tig+4]);
                uint32_t a3 = __float_as_uint(As[(R0+mt*16+g+8)*AS_S + kb+tig+4]);
                #pragma unroll
                for (int nt = 0; nt < 2; nt++)
                    mma_tf32(c[mt][nt], a0, a1, a2, a3, b0[nt], b1[nt]);
            }
        }
        __syncthreads();
    }

    #pragma unroll
    for (int mt = 0; mt < 2; mt++) {
        #pragma unroll
        for (int nt = 0; nt < 2; nt++) {
            int n = n0 + C0 + nt*8 + tig*2;
            float bx = 0.f, by = 0.f;
            if (bias) { bx = bias[n]; by = bias[n+1]; }
            int r0 = m0 + R0 + mt*16 + g;
            *(float2*)(C + (size_t)r0*ldc + n)     = make_float2(c[mt][nt][0]+bx, c[mt][nt][1]+by);
            *(float2*)(C + (size_t)(r0+8)*ldc + n) = make_float2(c[mt][nt][2]+bx, c[mt][nt][3]+by);
        }
    }
}

// ---------------- K2: bias via mma, smem-staged pw (coalesced float4) ----------------
#define BW_S 24
#define T_S  36
__global__ __launch_bounds__(256) void bias_mma_kernel(
    const float* __restrict__ pw, const float* __restrict__ ab)
{
    __shared__ float Ws[128*BW_S];             // gw transposed [d][h], tf32
    __shared__ __align__(16) float T[128*T_S]; // pw stage chunk; reused as score transpose
    __shared__ float Ts[16], Us[16];

    const int t = threadIdx.x;
    for (int l = t; l < 16*128; l += 256) {
        int h = l >> 7, d = l & 127;
        Ws[d*BW_S + h] = to_tf32(g_gw[h*DP + d]);
    }
    if (t < 16) Ts[t] = g_T[t];
    else if (t < 32) Us[t-16] = g_U[t-16];

    const int wid = t >> 5, lane = t & 31;
    const int g = lane >> 2, tig = lane & 3;
    const int r0 = wid*16 + g;                 // row within block (0..127)
    const size_t pb = (size_t)blockIdx.x * 128;

    const int srow = t >> 3, sc4 = (t & 7) * 4;

    float c[2][4];
    #pragma unroll
    for (int nt = 0; nt < 2; nt++)
        #pragma unroll
        for (int j = 0; j < 4; j++) c[nt][j] = 0.f;
    float s0 = 0.f, q0 = 0.f, s1 = 0.f, q1 = 0.f;

    __syncthreads();

    #pragma unroll
    for (int c0 = 0; c0 < DP; c0 += 32) {
        // stage 128 rows x 32 cols of pw, coalesced float4
        #pragma unroll
        for (int i = 0; i < 4; i++) {
            int row = srow + i*32;
            float4 v = *(const float4*)(pw + (pb+row)*DP + c0 + sc4);
            *(float4*)&T[row*T_S + sc4] = v;
        }
        __syncthreads();

        #pragma unroll
        for (int ks = 0; ks < 4; ks++) {
            int kb = ks*8;
            float a0 = T[(r0  )*T_S + kb+tig];
            float a1 = T[(r0+8)*T_S + kb+tig];
            float a2 = T[(r0  )*T_S + kb+tig+4];
            float a3 = T[(r0+8)*T_S + kb+tig+4];
            s0 += a0 + a2;  q0 += a0*a0 + a2*a2;
            s1 += a1 + a3;  q1 += a1*a1 + a3*a3;
            uint32_t u0 = __float_as_uint(to_tf32(a0));
            uint32_t u1 = __float_as_uint(to_tf32(a1));
            uint32_t u2 = __float_as_uint(to_tf32(a2));
            uint32_t u3 = __float_as_uint(to_tf32(a3));
            int kg = c0 + kb;
            #pragma unroll
            for (int nt = 0; nt < 2; nt++) {
                uint32_t b0 = __float_as_uint(Ws[(kg+tig  )*BW_S + nt*8 + g]);
                uint32_t b1 = __float_as_uint(Ws[(kg+tig+4)*BW_S + nt*8 + g]);
                mma_tf32(c[nt], u0, u1, u2, u3, b0, b1);
            }
        }
        __syncthreads();
    }

    s0 += __shfl_xor_sync(0xffffffffu, s0, 1); s0 += __shfl_xor_sync(0xffffffffu, s0, 2);
    q0 += __shfl_xor_sync(0xffffffffu, q0, 1); q0 += __shfl_xor_sync(0xffffffffu, q0, 2);
    s1 += __shfl_xor_sync(0xffffffffu, s1, 1); s1 += __shfl_xor_sync(0xffffffffu, s1, 2);
    q1 += __shfl_xor_sync(0xffffffffu, q1, 1); q1 += __shfl_xor_sync(0xffffffffu, q1, 2);

    float mu0 = s0 * (1.f/DP), mu1 = s1 * (1.f/DP);
    float rinv0 = rsqrtf(q0*(1.f/DP) - mu0*mu0 + 1e-5f);
    float rinv1 = rsqrtf(q1*(1.f/DP) - mu1*mu1 + 1e-5f);
    float ab0 = ab[pb + r0], ab1 = ab[pb + r0 + 8];

    float* Ss = T;   // reuse staging buffer for the transpose (stride 17)
    #pragma unroll
    for (int nt = 0; nt < 2; nt++) {
        #pragma unroll
        for (int j = 0; j < 2; j++) {
            int h = nt*8 + tig*2 + j;
            float Th = Ts[h], Uh = Us[h];
            Ss[(r0    )*17 + h] = rinv0*(c[nt][j  ] - mu0*Th) + Uh + ab0;
            Ss[(r0 + 8)*17 + h] = rinv1*(c[nt][2+j] - mu1*Th) + Uh + ab1;
        }
    }
    __syncthreads();
    for (int l = t; l < 2048; l += 256) {
        int h = l >> 7, r = l & 127;
        g_scores[(size_t)h*NN + pb + r] = Ss[r*17 + h];
    }
}

// ---------------- K3: flash attention, tf32 mma ----------------
#define SMEM_STRIDE 68
__global__ __launch_bounds__(256) void attn_mma_kernel()
{
    extern __shared__ float sm[];
    float* Qs = sm;
    float* Kc = Qs + 64*SMEM_STRIDE;
    float* Vc = Kc + 64*SMEM_STRIDE;
    float* Bc = Vc + 64*SMEM_STRIDE;
    float* Ps = Bc + 64*SMEM_STRIDE;
    float* redmax = Ps + 64*SMEM_STRIDE;
    float* redsum = redmax + 128;
    float* m_s = redsum + 128;
    float* l_s = m_s + 64;

    const int t   = threadIdx.x;
    const int h   = blockIdx.y;
    const int i0  = blockIdx.x * 64;
    const int wid = t >> 5, lane = t & 31;
    const int wm  = wid >> 1, wn = wid & 1;
    const int g   = lane >> 2, tig = lane & 3;
    const int R0  = wm * 16;
    const int C0  = wn * 32;
    const size_t hbase = (size_t)h * NN;

    for (int l = t*4; l < 64*64; l += 1024) {
        int r = l >> 6, d = l & 63;
        float4 v = *(const float4*)(g_q + (size_t)(i0+r)*INNER + h*DH + d);
        float* dst = Qs + r*SMEM_STRIDE + d;
        dst[0] = to_tf32(v.x); dst[1] = to_tf32(v.y);
        dst[2] = to_tf32(v.z); dst[3] = to_tf32(v.w);
    }
    if (t < 64) { m_s[t] = -1e30f; l_s[t] = 0.f; }
    __syncthreads();

    float oc[8][4];
    #pragma unroll
    for (int nt = 0; nt < 8; nt++)
        #pragma unroll
        for (int j = 0; j < 4; j++) oc[nt][j] = 0.f;

    for (int jc = 0; jc < NTOK; jc += 64) {
        for (int l = t*4; l < 64*64; l += 1024) {
            int r = l >> 6, d = l & 63;
            float4 kv = *(const float4*)(g_k + (size_t)(jc+r)*INNER + h*DH + d);
            float4 vv = *(const float4*)(g_v + (size_t)(jc+r)*INNER + h*DH + d);
            float4 bv = *(const float4*)(g_scores + hbase + (size_t)(i0+r)*NTOK + jc + d);
            float* kd = Kc + r*SMEM_STRIDE + d;
            float* vd = Vc + r*SMEM_STRIDE + d;
            float* bd = Bc + r*SMEM_STRIDE + d;
            kd[0]=to_tf32(kv.x); kd[1]=to_tf32(kv.y); kd[2]=to_tf32(kv.z); kd[3]=to_tf32(kv.w);
            vd[0]=to_tf32(vv.x); vd[1]=to_tf32(vv.y); vd[2]=to_tf32(vv.z); vd[3]=to_tf32(vv.w);
            bd[0]=bv.x; bd[1]=bv.y; bd[2]=bv.z; bd[3]=bv.w;
        }
        __syncthreads();

        float sc[4][4];
        #pragma unroll
        for (int nt = 0; nt < 4; nt++)
            #pragma unroll
            for (int j = 0; j < 4; j++) sc[nt][j] = 0.f;

        #pragma unroll
        for (int kk = 0; kk < 8; kk++) {
            int kb = kk*8;
            uint32_t a0 = __float_as_uint(Qs[(R0+g  )*SMEM_STRIDE + kb+tig]);
            uint32_t a1 = __float_as_uint(Qs[(R0+g+8)*SMEM_STRIDE + kb+tig]);
            uint32_t a2 = __float_as_uint(Qs[(R0+g  )*SMEM_STRIDE + kb+tig+4]);
            uint32_t a3 = __float_as_uint(Qs[(R0+g+8)*SMEM_STRIDE + kb+tig+4]);
            #pragma unroll
            for (int nt = 0; nt < 4; nt++) {
                uint32_t b0 = __float_as_uint(Kc[(C0+nt*8+g)*SMEM_STRIDE + kb+tig]);
                uint32_t b1 = __float_as_uint(Kc[(C0+nt*8+g)*SMEM_STRIDE + kb+tig+4]);
                mma_tf32(sc[nt], a0, a1, a2, a3, b0, b1);
            }
        }

        float rm0 = -1e30f, rm1 = -1e30f;
        #pragma unroll
        for (int nt = 0; nt < 4; nt++) {
            int cb = C0 + nt*8 + tig*2;
            sc[nt][0] = sc[nt][0]*0.125f + Bc[(R0+g  )*SMEM_STRIDE + cb];
            sc[nt][1] = sc[nt][1]*0.125f + Bc[(R0+g  )*SMEM_STRIDE + cb+1];
            sc[nt][2] = sc[nt][2]*0.125f + Bc[(R0+g+8)*SMEM_STRIDE + cb];
            sc[nt][3] = sc[nt][3]*0.125f + Bc[(R0+g+8)*SMEM_STRIDE + cb+1];
            rm0 = fmaxf(rm0, fmaxf(sc[nt][0], sc[nt][1]));
            rm1 = fmaxf(rm1, fmaxf(sc[nt][2], sc[nt][3]));
        }
        rm0 = fmaxf(rm0, __shfl_xor_sync(0xffffffffu, rm0, 1));
        rm0 = fmaxf(rm0, __shfl_xor_sync(0xffffffffu, rm0, 2));
        rm1 = fmaxf(rm1, __shfl_xor_sync(0xffffffffu, rm1, 1));
        rm1 = fmaxf(rm1, __shfl_xor_sync(0xffffffffu, rm1, 2));
        if (tig == 0) {
            redmax[wn*64 + R0+g  ] = rm0;
            redmax[wn*64 + R0+g+8] = rm1;
        }
        __syncthreads();

        float mo0 = m_s[R0+g], mo1 = m_s[R0+g+8];
        float mn0 = fmaxf(mo0, fmaxf(redmax[R0+g  ], redmax[64 + R0+g  ]));
        float mn1 = fmaxf(mo1, fmaxf(redmax[R0+g+8], redmax[64 + R0+g+8]));
        float al0 = __expf(mo0 - mn0);
        float al1 = __expf(mo1 - mn1);
        float ls0 = 0.f, ls1 = 0.f;
        #pragma unroll
        for (int nt = 0; nt < 4; nt++) {
            int cb = C0 + nt*8 + tig*2;
            float p0 = __expf(sc[nt][0] - mn0);
            float p1 = __expf(sc[nt][1] - mn0);
            float p2 = __expf(sc[nt][2] - mn1);
            float p3 = __expf(sc[nt][3] - mn1);
            ls0 += p0 + p1; ls1 += p2 + p3;
            Ps[(R0+g  )*SMEM_STRIDE + cb  ] = to_tf32(p0);
            Ps[(R0+g  )*SMEM_STRIDE + cb+1] = to_tf32(p1);
            Ps[(R0+g+8)*SMEM_STRIDE + cb  ] = to_tf32(p2);
            Ps[(R0+g+8)*SMEM_STRIDE + cb+1] = to_tf32(p3);
        }
        ls0 += __shfl_xor_sync(0xffffffffu, ls0, 1);
        ls0 += __shfl_xor_sync(0xffffffffu, ls0, 2);
        ls1 += __shfl_xor_sync(0xffffffffu, ls1, 1);
        ls1 += __shfl_xor_sync(0xffffffffu, ls1, 2);
        if (tig == 0) {
            redsum[wn*64 + R0+g  ] = ls0;
            redsum[wn*64 + R0+g+8] = ls1;
        }
        #pragma unroll
        for (int nt = 0; nt < 8; nt++) {
            oc[nt][0] *= al0; oc[nt][1] *= al0;
            oc[nt][2] *= al1; oc[nt][3] *= al1;
        }
        __syncthreads();

        if (t < 64) {
            float mo = m_s[t];
            float mn = fmaxf(mo, fmaxf(redmax[t], redmax[64+t]));
            l_s[t] = l_s[t]*__expf(mo - mn) + redsum[t] + redsum[64+t];
            m_s[t] = mn;
        }

        #pragma unroll
        for (int kk = 0; kk < 4; kk++) {
            int kb = C0 + kk*8;
            uint32_t a0 = __float_as_uint(Ps[(R0+g  )*SMEM_STRIDE + kb+tig]);
            uint32_t a1 = __float_as_uint(Ps[(R0+g+8)*SMEM_STRIDE + kb+tig]);
            uint32_t a2 = __float_as_uint(Ps[(R0+g  )*SMEM_STRIDE + kb+tig+4]);
            uint32_t a3 = __float_as_uint(Ps[(R0+g+8)*SMEM_STRIDE + kb+tig+4]);
            #pragma unroll
            for (int nt = 0; nt < 8; nt++) {
                uint32_t b0 = __float_as_uint(Vc[(kb+tig  )*SMEM_STRIDE + nt*8+g]);
                uint32_t b1 = __float_as_uint(Vc[(kb+tig+4)*SMEM_STRIDE + nt*8+g]);
                mma_tf32(oc[nt], a0, a1, a2, a3, b0, b1);
            }
        }
        __syncthreads();
    }

    if (wn == 1) {
        #pragma unroll
        for (int nt = 0; nt < 8; nt++) {
            int cb = nt*8 + tig*2;
            Ps[(R0+g  )*SMEM_STRIDE + cb  ] = oc[nt][0];
            Ps[(R0+g  )*SMEM_STRIDE + cb+1] = oc[nt][1];
            Ps[(R0+g+8)*SMEM_STRIDE + cb  ] = oc[nt][2];
            Ps[(R0+g+8)*SMEM_STRIDE + cb+1] = oc[nt][3];
        }
    }
    __syncthreads();
    if (wn == 0) {
        float inv0 = 1.f / l_s[R0+g];
        float inv1 = 1.f / l_s[R0+g+8];
        #pragma unroll
        for (int nt = 0; nt < 8; nt++) {
            int cb = nt*8 + tig*2;
            float2 v0, v1;
            v0.x = (oc[nt][0] + Ps[(R0+g  )*SMEM_STRIDE + cb  ]) * inv0;
            v0.y = (oc[nt][1] + Ps[(R0+g  )*SMEM_STRIDE + cb+1]) * inv0;
            v1.x = (oc[nt][2] + Ps[(R0+g+8)*SMEM_STRIDE + cb  ]) * inv1;
            v1.y = (oc[nt][3] + Ps[(R0+g+8)*SMEM_STRIDE + cb+1]) * inv1;
            *(float2*)(g_attnout + (size_t)(i0+R0+g  )*INNER + h*DH + cb) = v0;
            *(float2*)(g_attnout + (size_t)(i0+R0+g+8)*INNER + h*DH + cb) = v1;
        }
    }
}

// ---------------- launcher ----------------
extern "C" void kernel_launch(void* const* d_in, const int* in_sizes, int n_in,
                              void* d_out, int out_size)
{
    const float* x     = (const float*)d_in[0];
    const float* pw    = (const float*)d_in[1];
    const float* ab    = (const float*)d_in[2];
    const float* gamma = (const float*)d_in[3];
    const float* beta  = (const float*)d_in[4];
    const float* Wb    = (const float*)d_in[5];
    const float* Wq    = (const float*)d_in[6];
    const float* bq    = (const float*)d_in[7];
    const float* Wk    = (const float*)d_in[8];
    const float* Wv    = (const float*)d_in[9];
    const float* Wg    = (const float*)d_in[10];
    const float* Wo    = (const float*)d_in[11];
    float* out = (float*)d_out;

    float* dg;  cudaGetSymbolAddress((void**)&dg, g_g);
    float* dao; cudaGetSymbolAddress((void**)&dao, g_attnout);

    prep_kernel<<<1, 256>>>(gamma, beta, Wb);

    proj4_kernel<<<dim3(INNER/64, NTOK/64, 4), 256>>>(x, Wq, bq, Wk, Wv, Wg);

    bias_mma_kernel<<<NN/128, 256>>>(pw, ab);

    const int smem_bytes = (5*64*SMEM_STRIDE + 2*64 + 2*64 + 64 + 64) * 4;
    cudaFuncSetAttribute(attn_mma_kernel, cudaFuncAttributeMaxDynamicSharedMemorySize, smem_bytes);
    attn_mma_kernel<<<dim3(NTOK/64, NH), 256, smem_bytes>>>();

    gemm_tf32<INNER, true><<<dim3(DS/64, NTOK/64), 256>>>(dao, dg, Wo, nullptr, out, DS, DS);
}

// round 6
// speedup vs baseline: 3.4288x; 1.2336x over previous
#include <cuda_runtime.h>
#include <cstdint>

#define NTOK  1024
#define DS    384
#define DP    128
#define NH    16
#define DH    64
#define INNER 1024
#define NN    (NTOK*NTOK)

// ---------------- scratch ----------------
__device__ float g_q[NTOK*INNER];
__device__ float g_k[NTOK*INNER];
__device__ float g_v[NTOK*INNER];
__device__ float g_g[NTOK*INNER];
__device__ float g_scores[(size_t)NH*NN];
__device__ float g_attnout[NTOK*INNER];
__device__ float g_gw[NH*DP];
__device__ float g_T[NH];
__device__ float g_U[NH];

__device__ __forceinline__ float to_tf32(float x) {
    float y;
    asm("cvt.rna.tf32.f32 %0, %1;" : "=f"(y) : "f"(x));
    return y;
}
__device__ __forceinline__ void mma_tf32(float c[4],
    uint32_t a0, uint32_t a1, uint32_t a2, uint32_t a3,
    uint32_t b0, uint32_t b1)
{
    asm volatile("mma.sync.aligned.m16n8k8.row.col.f32.tf32.tf32.f32 "
        "{%0,%1,%2,%3}, {%4,%5,%6,%7}, {%8,%9}, {%0,%1,%2,%3};"
        : "+f"(c[0]), "+f"(c[1]), "+f"(c[2]), "+f"(c[3])
        : "r"(a0), "r"(a1), "r"(a2), "r"(a3), "r"(b0), "r"(b1));
}
__device__ __forceinline__ void cp16(float* dst, const float* src) {
    uint32_t s = (uint32_t)__cvta_generic_to_shared(dst);
    asm volatile("cp.async.cg.shared.global [%0], [%1], 16;" :: "r"(s), "l"(src));
}
#define CP_COMMIT() asm volatile("cp.async.commit_group;")

// ---------------- K0: tiny precompute ----------------
__global__ void prep_kernel(const float* __restrict__ gamma,
                            const float* __restrict__ beta,
                            const float* __restrict__ Wb)
{
    int t = threadIdx.x;
    for (int l = t; l < NH*DP; l += blockDim.x) {
        int h = l / DP, d = l % DP;
        g_gw[h*DP + d] = gamma[d] * Wb[d*NH + h];
    }
    if (t < 2*NH) {
        int h = t % NH;
        const float* src = (t < NH) ? gamma : beta;
        float s = 0.f;
        for (int d = 0; d < DP; d++) s += src[d] * Wb[d*NH + h];
        if (t < NH) g_T[h] = s; else g_U[h] = s;
    }
}

// ---------------- fused proj(4x) + bias kernel ----------------
#define AS_S 20
#define BS_S 72
#define WS_S 24
#define T_S  36

__device__ __forceinline__ void proj_body(float* smem,
    const float* __restrict__ X, const float* __restrict__ B,
    const float* __restrict__ bq, int sel, int bx, int by)
{
    float* As = smem;             // 64*AS_S
    float* Bs = smem + 64*AS_S;   // 16*BS_S
    float* C = (sel==0) ? g_q : (sel==1) ? g_k : (sel==2) ? g_v : g_g;

    const int t = threadIdx.x;
    const int m0 = by * 64;
    const int n0 = bx * 64;
    const int wid = t >> 5, lane = t & 31;
    const int wm = wid & 1, wn = wid >> 1;
    const int g = lane >> 2, tig = lane & 3;
    const int R0 = wm * 32, C0 = wn * 16;

    float c[2][2][4];
    #pragma unroll
    for (int mt = 0; mt < 2; mt++)
        #pragma unroll
        for (int nt = 0; nt < 2; nt++)
            #pragma unroll
            for (int j = 0; j < 4; j++) c[mt][nt][j] = 0.f;

    const int am = t >> 2, akq = (t & 3) * 4;
    const int bk = t >> 4, bn4 = (t & 15) * 4;

    for (int k0 = 0; k0 < DS; k0 += 16) {
        {
            float4 av = *(const float4*)(X + (size_t)(m0+am)*DS + k0 + akq);
            float* d = As + am*AS_S + akq;
            d[0]=to_tf32(av.x); d[1]=to_tf32(av.y); d[2]=to_tf32(av.z); d[3]=to_tf32(av.w);
        }
        {
            float4 bv = *(const float4*)(B + (size_t)(k0+bk)*INNER + n0 + bn4);
            float* d = Bs + bk*BS_S + bn4;
            d[0]=to_tf32(bv.x); d[1]=to_tf32(bv.y); d[2]=to_tf32(bv.z); d[3]=to_tf32(bv.w);
        }
        __syncthreads();
        #pragma unroll
        for (int kk = 0; kk < 2; kk++) {
            int kb = kk * 8;
            uint32_t b0[2], b1[2];
            #pragma unroll
            for (int nt = 0; nt < 2; nt++) {
                b0[nt] = __float_as_uint(Bs[(kb+tig  )*BS_S + C0 + nt*8 + g]);
                b1[nt] = __float_as_uint(Bs[(kb+tig+4)*BS_S + C0 + nt*8 + g]);
            }
            #pragma unroll
            for (int mt = 0; mt < 2; mt++) {
                uint32_t a0 = __float_as_uint(As[(R0+mt*16+g  )*AS_S + kb+tig]);
                uint32_t a1 = __float_as_uint(As[(R0+mt*16+g+8)*AS_S + kb+tig]);
                uint32_t a2 = __float_as_uint(As[(R0+mt*16+g  )*AS_S + kb+tig+4]);
                uint32_t a3 = __float_as_uint(As[(R0+mt*16+g+8)*AS_S + kb+tig+4]);
                #pragma unroll
                for (int nt = 0; nt < 2; nt++)
                    mma_tf32(c[mt][nt], a0, a1, a2, a3, b0[nt], b1[nt]);
            }
        }
        __syncthreads();
    }

    #pragma unroll
    for (int mt = 0; mt < 2; mt++) {
        #pragma unroll
        for (int nt = 0; nt < 2; nt++) {
            int n = n0 + C0 + nt*8 + tig*2;
            float bx2 = 0.f, by2 = 0.f;
            if (sel == 0) { bx2 = bq[n]; by2 = bq[n+1]; }
            int r0 = m0 + R0 + mt*16 + g;
            *(float2*)(C + (size_t)r0*INNER + n)     = make_float2(c[mt][nt][0]+bx2, c[mt][nt][1]+by2);
            *(float2*)(C + (size_t)(r0+8)*INNER + n) = make_float2(c[mt][nt][2]+bx2, c[mt][nt][3]+by2);
        }
    }
}

__device__ __forceinline__ void bias_body(float* smem,
    const float* __restrict__ pw, const float* __restrict__ ab, int bid)
{
    float* Ws = smem;               // 128*WS_S
    float* T  = smem + 128*WS_S;    // 2 * 128*T_S

    const int t = threadIdx.x;
    const size_t pb = (size_t)bid * 128;
    const int srow = t >> 3, sc4 = (t & 7) * 4;

    // prologue: cp.async chunk0, then Ws load, then chunk1
    #pragma unroll
    for (int i = 0; i < 4; i++) {
        int row = srow + i*32;
        cp16(&T[row*T_S + sc4], pw + (pb+row)*DP + sc4);
    }
    CP_COMMIT();

    for (int l = t; l < 16*128; l += 256) {
        int h = l >> 7, d = l & 127;
        Ws[d*WS_S + h] = to_tf32(g_gw[h*DP + d]);
    }

    #pragma unroll
    for (int i = 0; i < 4; i++) {
        int row = srow + i*32;
        cp16(&T[128*T_S + row*T_S + sc4], pw + (pb+row)*DP + 32 + sc4);
    }
    CP_COMMIT();

    const int wid = t >> 5, lane = t & 31;
    const int g = lane >> 2, tig = lane & 3;
    const int r0 = wid*16 + g;

    float c[2][4];
    #pragma unroll
    for (int nt = 0; nt < 2; nt++)
        #pragma unroll
        for (int j = 0; j < 4; j++) c[nt][j] = 0.f;
    float s0 = 0.f, q0 = 0.f, s1 = 0.f, q1 = 0.f;

    for (int cc = 0; cc < 4; cc++) {
        if (cc < 3) asm volatile("cp.async.wait_group 1;");
        else        asm volatile("cp.async.wait_group 0;");
        __syncthreads();
        float* Tb = T + (cc & 1) * 128*T_S;

        #pragma unroll
        for (int ks = 0; ks < 4; ks++) {
            int kb = ks*8;
            float a0 = Tb[(r0  )*T_S + kb+tig];
            float a1 = Tb[(r0+8)*T_S + kb+tig];
            float a2 = Tb[(r0  )*T_S + kb+tig+4];
            float a3 = Tb[(r0+8)*T_S + kb+tig+4];
            s0 += a0 + a2;  q0 += a0*a0 + a2*a2;
            s1 += a1 + a3;  q1 += a1*a1 + a3*a3;
            uint32_t u0 = __float_as_uint(to_tf32(a0));
            uint32_t u1 = __float_as_uint(to_tf32(a1));
            uint32_t u2 = __float_as_uint(to_tf32(a2));
            uint32_t u3 = __float_as_uint(to_tf32(a3));
            int kg = cc*32 + kb;
            #pragma unroll
            for (int nt = 0; nt < 2; nt++) {
                uint32_t b0 = __float_as_uint(Ws[(kg+tig  )*WS_S + nt*8 + g]);
                uint32_t b1 = __float_as_uint(Ws[(kg+tig+4)*WS_S + nt*8 + g]);
                mma_tf32(c[nt], u0, u1, u2, u3, b0, b1);
            }
        }
        __syncthreads();
        if (cc + 2 < 4) {
            #pragma unroll
            for (int i = 0; i < 4; i++) {
                int row = srow + i*32;
                cp16(&T[(cc&1)*128*T_S + row*T_S + sc4], pw + (pb+row)*DP + (cc+2)*32 + sc4);
            }
            CP_COMMIT();
        }
    }

    s0 += __shfl_xor_sync(0xffffffffu, s0, 1); s0 += __shfl_xor_sync(0xffffffffu, s0, 2);
    q0 += __shfl_xor_sync(0xffffffffu, q0, 1); q0 += __shfl_xor_sync(0xffffffffu, q0, 2);
    s1 += __shfl_xor_sync(0xffffffffu, s1, 1); s1 += __shfl_xor_sync(0xffffffffu, s1, 2);
    q1 += __shfl_xor_sync(0xffffffffu, q1, 1); q1 += __shfl_xor_sync(0xffffffffu, q1, 2);

    float mu0 = s0 * (1.f/DP), mu1 = s1 * (1.f/DP);
    float rinv0 = rsqrtf(q0*(1.f/DP) - mu0*mu0 + 1e-5f);
    float rinv1 = rsqrtf(q1*(1.f/DP) - mu1*mu1 + 1e-5f);
    float ab0 = ab[pb + r0], ab1 = ab[pb + r0 + 8];

    float* Ss = T;   // reuse (all cp.async retired)
    #pragma unroll
    for (int nt = 0; nt < 2; nt++) {
        #pragma unroll
        for (int j = 0; j < 2; j++) {
            int h = nt*8 + tig*2 + j;
            float Th = g_T[h], Uh = g_U[h];
            Ss[(r0    )*17 + h] = rinv0*(c[nt][j  ] - mu0*Th) + Uh + ab0;
            Ss[(r0 + 8)*17 + h] = rinv1*(c[nt][2+j] - mu1*Th) + Uh + ab1;
        }
    }
    __syncthreads();
    for (int l = t; l < 2048; l += 256) {
        int h = l >> 7, r = l & 127;
        g_scores[(size_t)h*NN + pb + r] = Ss[r*17 + h];
    }
}

__global__ __launch_bounds__(256) void fused_pb_kernel(
    const float* __restrict__ X,
    const float* __restrict__ Wq, const float* __restrict__ bq,
    const float* __restrict__ Wk, const float* __restrict__ Wv,
    const float* __restrict__ Wg,
    const float* __restrict__ pw, const float* __restrict__ ab)
{
    extern __shared__ float smem[];
    int bid = blockIdx.x;
    if (bid < 1024) {
        int sel = bid >> 8;
        int rem = bid & 255;
        const float* B = (sel==0) ? Wq : (sel==1) ? Wk : (sel==2) ? Wv : Wg;
        proj_body(smem, X, B, bq, sel, rem & 15, rem >> 4);
    } else {
        bias_body(smem, pw, ab, bid - 1024);
    }
}

// ---------------- outproj GEMM ----------------
template<int KD, bool GATE>
__global__ __launch_bounds__(256) void gemm_tf32(
    const float* __restrict__ A, const float* __restrict__ Gt,
    const float* __restrict__ B, const float* __restrict__ bias,
    float* __restrict__ C, int ldb, int ldc)
{
    __shared__ __align__(16) float As[64*AS_S];
    __shared__ __align__(16) float Bs[16*BS_S];

    const int t = threadIdx.x;
    const int m0 = blockIdx.y * 64;
    const int n0 = blockIdx.x * 64;
    const int wid = t >> 5, lane = t & 31;
    const int wm = wid & 1, wn = wid >> 1;
    const int g = lane >> 2, tig = lane & 3;
    const int R0 = wm * 32, C0 = wn * 16;

    float c[2][2][4];
    #pragma unroll
    for (int mt = 0; mt < 2; mt++)
        #pragma unroll
        for (int nt = 0; nt < 2; nt++)
            #pragma unroll
            for (int j = 0; j < 4; j++) c[mt][nt][j] = 0.f;

    const int am = t >> 2, akq = (t & 3) * 4;
    const int bk = t >> 4, bn4 = (t & 15) * 4;

    for (int k0 = 0; k0 < KD; k0 += 16) {
        {
            float4 av = *(const float4*)(A + (size_t)(m0+am)*KD + k0 + akq);
            if (GATE) {
                float4 gv = *(const float4*)(Gt + (size_t)(m0+am)*KD + k0 + akq);
                av.x *= 1.f/(1.f + __expf(-gv.x));
                av.y *= 1.f/(1.f + __expf(-gv.y));
                av.z *= 1.f/(1.f + __expf(-gv.z));
                av.w *= 1.f/(1.f + __expf(-gv.w));
            }
            float* d = As + am*AS_S + akq;
            d[0]=to_tf32(av.x); d[1]=to_tf32(av.y); d[2]=to_tf32(av.z); d[3]=to_tf32(av.w);
        }
        {
            float4 bv = *(const float4*)(B + (size_t)(k0+bk)*ldb + n0 + bn4);
            float* d = Bs + bk*BS_S + bn4;
            d[0]=to_tf32(bv.x); d[1]=to_tf32(bv.y); d[2]=to_tf32(bv.z); d[3]=to_tf32(bv.w);
        }
        __syncthreads();
        #pragma unroll
        for (int kk = 0; kk < 2; kk++) {
            int kb = kk * 8;
            uint32_t b0[2], b1[2];
            #pragma unroll
            for (int nt = 0; nt < 2; nt++) {
                b0[nt] = __float_as_uint(Bs[(kb+tig  )*BS_S + C0 + nt*8 + g]);
                b1[nt] = __float_as_uint(Bs[(kb+tig+4)*BS_S + C0 + nt*8 + g]);
            }
            #pragma unroll
            for (int mt = 0; mt < 2; mt++) {
                uint32_t a0 = __float_as_uint(As[(R0+mt*16+g  )*AS_S + kb+tig]);
                uint32_t a1 = __float_as_uint(As[(R0+mt*16+g+8)*AS_S + kb+tig]);
                uint32_t a2 = __float_as_uint(As[(R0+mt*16+g  )*AS_S + kb+tig+4]);
                uint32_t a3 = __float_as_uint(As[(R0+mt*16+g+8)*AS_S + kb+tig+4]);
                #pragma unroll
                for (int nt = 0; nt < 2; nt++)
                    mma_tf32(c[mt][nt], a0, a1, a2, a3, b0[nt], b1[nt]);
            }
        }
        __syncthreads();
    }

    #pragma unroll
    for (int mt = 0; mt < 2; mt++) {
        #pragma unroll
        for (int nt = 0; nt < 2; nt++) {
            int n = n0 + C0 + nt*8 + tig*2;
            float bx = 0.f, by = 0.f;
            if (bias) { bx = bias[n]; by = bias[n+1]; }
            int r0 = m0 + R0 + mt*16 + g;
            *(float2*)(C + (size_t)r0*ldc + n)     = make_float2(c[mt][nt][0]+bx, c[mt][nt][1]+by);
            *(float2*)(C + (size_t)(r0+8)*ldc + n) = make_float2(c[mt][nt][2]+bx, c[mt][nt][3]+by);
        }
    }
}

// ---------------- attn v2: 128 rows/CTA, warp-local softmax, Q in regs ----------------
#define KS  68
#define VS  72
#define BBS 68
#define PSS 68
__global__ __launch_bounds__(256, 1) void attn2_kernel()
{
    extern __shared__ float sm2[];
    float* Kc = sm2;                    // 64*KS
    float* Vc = Kc + 64*KS;             // 64*VS
    float* Bc = Vc + 64*VS;             // 2 * 128*BBS
    float* Ps = Bc + 2*128*BBS;         // 128*PSS

    const int t = threadIdx.x;
    const int h = blockIdx.y;
    const int i0 = blockIdx.x * 128;
    const int wid = t >> 5, lane = t & 31;
    const int g = lane >> 2, tig = lane & 3;
    const int R0 = wid * 16;
    const float* bsrc = g_scores + (size_t)h * NN + (size_t)i0 * NTOK;

    // Q fragments in registers (reused across all key chunks)
    uint32_t qf[8][4];
    {
        const float* q0 = g_q + (size_t)(i0 + R0 + g    ) * INNER + h*DH;
        const float* q1 = g_q + (size_t)(i0 + R0 + g + 8) * INNER + h*DH;
        #pragma unroll
        for (int kk = 0; kk < 8; kk++) {
            qf[kk][0] = __float_as_uint(to_tf32(q0[kk*8 + tig]));
            qf[kk][1] = __float_as_uint(to_tf32(q1[kk*8 + tig]));
            qf[kk][2] = __float_as_uint(to_tf32(q0[kk*8 + tig + 4]));
            qf[kk][3] = __float_as_uint(to_tf32(q1[kk*8 + tig + 4]));
        }
    }

    float oc[8][4];
    #pragma unroll
    for (int nt = 0; nt < 8; nt++)
        #pragma unroll
        for (int j = 0; j < 4; j++) oc[nt][j] = 0.f;
    float m0v = -1e30f, m1v = -1e30f, l0v = 0.f, l1v = 0.f;

    // prologue: bias chunk 0 via cp.async
    {
        const int br = t >> 4, bc4 = (t & 15) * 4;
        #pragma unroll
        for (int j = 0; j < 8; j++) {
            int row = br + j*16;
            cp16(Bc + row*BBS + bc4, bsrc + (size_t)row*NTOK + bc4);
        }
        CP_COMMIT();
    }

    for (int c = 0; c < 16; c++) {
        const int jc = c * 64;
        if (c + 1 < 16) {
            float* dst = Bc + ((c+1)&1)*128*BBS;
            const float* src = bsrc + jc + 64;
            const int br = t >> 4, bc4 = (t & 15) * 4;
            #pragma unroll
            for (int j = 0; j < 8; j++) {
                int row = br + j*16;
                cp16(dst + row*BBS + bc4, src + (size_t)row*NTOK + bc4);
            }
            CP_COMMIT();
        }
        // stage K/V (tf32) for chunk c
        #pragma unroll
        for (int l = t*4; l < 64*64; l += 1024) {
            int r = l >> 6, d = l & 63;
            float4 kv = *(const float4*)(g_k + (size_t)(jc + r)*INNER + h*DH + d);
            float4 vv = *(const float4*)(g_v + (size_t)(jc + r)*INNER + h*DH + d);
            float* kd = Kc + r*KS + d;
            float* vd = Vc + r*VS + d;
            kd[0]=to_tf32(kv.x); kd[1]=to_tf32(kv.y); kd[2]=to_tf32(kv.z); kd[3]=to_tf32(kv.w);
            vd[0]=to_tf32(vv.x); vd[1]=to_tf32(vv.y); vd[2]=to_tf32(vv.z); vd[3]=to_tf32(vv.w);
        }
        if (c < 15) asm volatile("cp.async.wait_group 1;");
        else        asm volatile("cp.async.wait_group 0;");
        __syncthreads();
        const float* Bcur = Bc + (c&1)*128*BBS;

        // ---- S = Q K^T : 16 rows x 64 keys per warp ----
        float sc[8][4];
        #pragma unroll
        for (int nt = 0; nt < 8; nt++)
            #pragma unroll
            for (int j = 0; j < 4; j++) sc[nt][j] = 0.f;
        #pragma unroll
        for (int kk = 0; kk < 8; kk++) {
            #pragma unroll
            for (int nt = 0; nt < 8; nt++) {
                uint32_t b0 = __float_as_uint(Kc[(nt*8+g)*KS + kk*8+tig]);
                uint32_t b1 = __float_as_uint(Kc[(nt*8+g)*KS + kk*8+tig+4]);
                mma_tf32(sc[nt], qf[kk][0], qf[kk][1], qf[kk][2], qf[kk][3], b0, b1);
            }
        }

        // ---- scale + bias + row max (warp-local) ----
        float rm0 = -1e30f, rm1 = -1e30f;
        #pragma unroll
        for (int nt = 0; nt < 8; nt++) {
            int cb = nt*8 + tig*2;
            sc[nt][0] = sc[nt][0]*0.125f + Bcur[(R0+g  )*BBS + cb];
            sc[nt][1] = sc[nt][1]*0.125f + Bcur[(R0+g  )*BBS + cb+1];
            sc[nt][2] = sc[nt][2]*0.125f + Bcur[(R0+g+8)*BBS + cb];
            sc[nt][3] = sc[nt][3]*0.125f + Bcur[(R0+g+8)*BBS + cb+1];
            rm0 = fmaxf(rm0, fmaxf(sc[nt][0], sc[nt][1]));
            rm1 = fmaxf(rm1, fmaxf(sc[nt][2], sc[nt][3]));
        }
        rm0 = fmaxf(rm0, __shfl_xor_sync(0xffffffffu, rm0, 1));
        rm0 = fmaxf(rm0, __shfl_xor_sync(0xffffffffu, rm0, 2));
        rm1 = fmaxf(rm1, __shfl_xor_sync(0xffffffffu, rm1, 1));
        rm1 = fmaxf(rm1, __shfl_xor_sync(0xffffffffu, rm1, 2));

        float mn0 = fmaxf(m0v, rm0), mn1 = fmaxf(m1v, rm1);
        float al0 = __expf(m0v - mn0), al1 = __expf(m1v - mn1);
        m0v = mn0; m1v = mn1;

        float ls0 = 0.f, ls1 = 0.f;
        #pragma unroll
        for (int nt = 0; nt < 8; nt++) {
            int cb = nt*8 + tig*2;
            float p0 = __expf(sc[nt][0] - mn0);
            float p1 = __expf(sc[nt][1] - mn0);
            float p2 = __expf(sc[nt][2] - mn1);
            float p3 = __expf(sc[nt][3] - mn1);
            ls0 += p0 + p1; ls1 += p2 + p3;
            Ps[(R0+g  )*PSS + cb  ] = to_tf32(p0);
            Ps[(R0+g  )*PSS + cb+1] = to_tf32(p1);
            Ps[(R0+g+8)*PSS + cb  ] = to_tf32(p2);
            Ps[(R0+g+8)*PSS + cb+1] = to_tf32(p3);
        }
        ls0 += __shfl_xor_sync(0xffffffffu, ls0, 1);
        ls0 += __shfl_xor_sync(0xffffffffu, ls0, 2);
        ls1 += __shfl_xor_sync(0xffffffffu, ls1, 1);
        ls1 += __shfl_xor_sync(0xffffffffu, ls1, 2);
        l0v = l0v*al0 + ls0;
        l1v = l1v*al1 + ls1;
        #pragma unroll
        for (int nt = 0; nt < 8; nt++) {
            oc[nt][0] *= al0; oc[nt][1] *= al0;
            oc[nt][2] *= al1; oc[nt][3] *= al1;
        }
        __syncwarp();

        // ---- O += P V ----
        #pragma unroll
        for (int kk = 0; kk < 8; kk++) {
            int kb = kk*8;
            uint32_t a0 = __float_as_uint(Ps[(R0+g  )*PSS + kb+tig]);
            uint32_t a1 = __float_as_uint(Ps[(R0+g+8)*PSS + kb+tig]);
            uint32_t a2 = __float_as_uint(Ps[(R0+g  )*PSS + kb+tig+4]);
            uint32_t a3 = __float_as_uint(Ps[(R0+g+8)*PSS + kb+tig+4]);
            #pragma unroll
            for (int nt = 0; nt < 8; nt++) {
                uint32_t b0 = __float_as_uint(Vc[(kb+tig  )*VS + nt*8+g]);
                uint32_t b1 = __float_as_uint(Vc[(kb+tig+4)*VS + nt*8+g]);
                mma_tf32(oc[nt], a0, a1, a2, a3, b0, b1);
            }
        }
        __syncthreads();
    }

    float inv0 = 1.f/l0v, inv1 = 1.f/l1v;
    #pragma unroll
    for (int nt = 0; nt < 8; nt++) {
        int cb = nt*8 + tig*2;
        *(float2*)(g_attnout + (size_t)(i0+R0+g  )*INNER + h*DH + cb) =
            make_float2(oc[nt][0]*inv0, oc[nt][1]*inv0);
        *(float2*)(g_attnout + (size_t)(i0+R0+g+8)*INNER + h*DH + cb) =
            make_float2(oc[nt][2]*inv1, oc[nt][3]*inv1);
    }
}

// ---------------- launcher ----------------
extern "C" void kernel_launch(void* const* d_in, const int* in_sizes, int n_in,
                              void* d_out, int out_size)
{
    const float* x     = (const float*)d_in[0];
    const float* pw    = (const float*)d_in[1];
    const float* ab    = (const float*)d_in[2];
    const float* gamma = (const float*)d_in[3];
    const float* beta  = (const float*)d_in[4];
    const float* Wb    = (const float*)d_in[5];
    const float* Wq    = (const float*)d_in[6];
    const float* bq    = (const float*)d_in[7];
    const float* Wk    = (const float*)d_in[8];
    const float* Wv    = (const float*)d_in[9];
    const float* Wg    = (const float*)d_in[10];
    const float* Wo    = (const float*)d_in[11];
    float* out = (float*)d_out;

    float* dg;  cudaGetSymbolAddress((void**)&dg, g_g);
    float* dao; cudaGetSymbolAddress((void**)&dao, g_attnout);

    prep_kernel<<<1, 256>>>(gamma, beta, Wb);

    const int pb_smem = (128*WS_S + 2*128*T_S) * 4;   // 49152
    cudaFuncSetAttribute(fused_pb_kernel, cudaFuncAttributeMaxDynamicSharedMemorySize, pb_smem);
    fused_pb_kernel<<<1024 + NN/128, 256, pb_smem>>>(x, Wq, bq, Wk, Wv, Wg, pw, ab);

    const int attn_smem = (64*KS + 64*VS + 2*128*BBS + 128*PSS) * 4;  // 140288
    cudaFuncSetAttribute(attn2_kernel, cudaFuncAttributeMaxDynamicSharedMemorySize, attn_smem);
    attn2_kernel<<<dim3(NTOK/128, NH), 256, attn_smem>>>();

    gemm_tf32<INNER, true><<<dim3(DS/64, NTOK/64), 256>>>(dao, dg, Wo, nullptr, out, DS, DS);
}

// round 10
// speedup vs baseline: 4.2702x; 1.2454x over previous
#include <cuda_runtime.h>
#include <cstdint>

#define NTOK  1024
#define DS    384
#define DP    128
#define NH    16
#define DH    64
#define INNER 1024
#define NN    (NTOK*NTOK)

// ---------------- scratch ----------------
__device__ float g_q[NTOK*INNER];
__device__ float g_k[NTOK*INNER];
__device__ float g_v[NTOK*INNER];
__device__ float g_g[NTOK*INNER];
__device__ float g_scores[(size_t)NH*NN];
__device__ float g_attnout[NTOK*INNER];     // now holds attnout * sigmoid(gate)
__device__ float g_gw[NH*DP];
__device__ float g_T[NH];
__device__ float g_U[NH];

__device__ __forceinline__ float to_tf32(float x) {
    float y;
    asm("cvt.rna.tf32.f32 %0, %1;" : "=f"(y) : "f"(x));
    return y;
}
__device__ __forceinline__ void mma_tf32(float c[4],
    uint32_t a0, uint32_t a1, uint32_t a2, uint32_t a3,
    uint32_t b0, uint32_t b1)
{
    asm volatile("mma.sync.aligned.m16n8k8.row.col.f32.tf32.tf32.f32 "
        "{%0,%1,%2,%3}, {%4,%5,%6,%7}, {%8,%9}, {%0,%1,%2,%3};"
        : "+f"(c[0]), "+f"(c[1]), "+f"(c[2]), "+f"(c[3])
        : "r"(a0), "r"(a1), "r"(a2), "r"(a3), "r"(b0), "r"(b1));
}
__device__ __forceinline__ void cp16(float* dst, const float* src) {
    uint32_t s = (uint32_t)__cvta_generic_to_shared(dst);
    asm volatile("cp.async.cg.shared.global [%0], [%1], 16;" :: "r"(s), "l"(src));
}
#define CP_COMMIT() asm volatile("cp.async.commit_group;")

// ---------------- K0: tiny precompute ----------------
__global__ void prep_kernel(const float* __restrict__ gamma,
                            const float* __restrict__ beta,
                            const float* __restrict__ Wb)
{
    int t = threadIdx.x;
    for (int l = t; l < NH*DP; l += blockDim.x) {
        int h = l / DP, d = l % DP;
        g_gw[h*DP + d] = gamma[d] * Wb[d*NH + h];
    }
    if (t < 2*NH) {
        int h = t % NH;
        const float* src = (t < NH) ? gamma : beta;
        float s = 0.f;
        for (int d = 0; d < DP; d++) s += src[d] * Wb[d*NH + h];
        if (t < NH) g_T[h] = s; else g_U[h] = s;
    }
}

// ---------------- fused proj(4x) + bias kernel ----------------
#define AS_S 20
#define BS_S 72
#define WS_S 24
#define T_S  36

__device__ __forceinline__ void proj_body(float* smem,
    const float* __restrict__ X, const float* __restrict__ B,
    const float* __restrict__ bq, int sel, int bx, int by)
{
    float* As = smem;
    float* Bs = smem + 64*AS_S;
    float* C = (sel==0) ? g_q : (sel==1) ? g_k : (sel==2) ? g_v : g_g;

    const int t = threadIdx.x;
    const int m0 = by * 64;
    const int n0 = bx * 64;
    const int wid = t >> 5, lane = t & 31;
    const int wm = wid & 1, wn = wid >> 1;
    const int g = lane >> 2, tig = lane & 3;
    const int R0 = wm * 32, C0 = wn * 16;

    float c[2][2][4];
    #pragma unroll
    for (int mt = 0; mt < 2; mt++)
        #pragma unroll
        for (int nt = 0; nt < 2; nt++)
            #pragma unroll
            for (int j = 0; j < 4; j++) c[mt][nt][j] = 0.f;

    const int am = t >> 2, akq = (t & 3) * 4;
    const int bk = t >> 4, bn4 = (t & 15) * 4;

    for (int k0 = 0; k0 < DS; k0 += 16) {
        {
            float4 av = *(const float4*)(X + (size_t)(m0+am)*DS + k0 + akq);
            float* d = As + am*AS_S + akq;
            d[0]=to_tf32(av.x); d[1]=to_tf32(av.y); d[2]=to_tf32(av.z); d[3]=to_tf32(av.w);
        }
        {
            float4 bv = *(const float4*)(B + (size_t)(k0+bk)*INNER + n0 + bn4);
            float* d = Bs + bk*BS_S + bn4;
            d[0]=to_tf32(bv.x); d[1]=to_tf32(bv.y); d[2]=to_tf32(bv.z); d[3]=to_tf32(bv.w);
        }
        __syncthreads();
        #pragma unroll
        for (int kk = 0; kk < 2; kk++) {
            int kb = kk * 8;
            uint32_t b0[2], b1[2];
            #pragma unroll
            for (int nt = 0; nt < 2; nt++) {
                b0[nt] = __float_as_uint(Bs[(kb+tig  )*BS_S + C0 + nt*8 + g]);
                b1[nt] = __float_as_uint(Bs[(kb+tig+4)*BS_S + C0 + nt*8 + g]);
            }
            #pragma unroll
            for (int mt = 0; mt < 2; mt++) {
                uint32_t a0 = __float_as_uint(As[(R0+mt*16+g  )*AS_S + kb+tig]);
                uint32_t a1 = __float_as_uint(As[(R0+mt*16+g+8)*AS_S + kb+tig]);
                uint32_t a2 = __float_as_uint(As[(R0+mt*16+g  )*AS_S + kb+tig+4]);
                uint32_t a3 = __float_as_uint(As[(R0+mt*16+g+8)*AS_S + kb+tig+4]);
                #pragma unroll
                for (int nt = 0; nt < 2; nt++)
                    mma_tf32(c[mt][nt], a0, a1, a2, a3, b0[nt], b1[nt]);
            }
        }
        __syncthreads();
    }

    #pragma unroll
    for (int mt = 0; mt < 2; mt++) {
        #pragma unroll
        for (int nt = 0; nt < 2; nt++) {
            int n = n0 + C0 + nt*8 + tig*2;
            float bx2 = 0.f, by2 = 0.f;
            if (sel == 0) { bx2 = bq[n]; by2 = bq[n+1]; }
            int r0 = m0 + R0 + mt*16 + g;
            *(float2*)(C + (size_t)r0*INNER + n)     = make_float2(c[mt][nt][0]+bx2, c[mt][nt][1]+by2);
            *(float2*)(C + (size_t)(r0+8)*INNER + n) = make_float2(c[mt][nt][2]+bx2, c[mt][nt][3]+by2);
        }
    }
}

__device__ __forceinline__ void bias_body(float* smem,
    const float* __restrict__ pw, const float* __restrict__ ab, int bid)
{
    float* Ws = smem;
    float* T  = smem + 128*WS_S;

    const int t = threadIdx.x;
    const size_t pb = (size_t)bid * 128;
    const int srow = t >> 3, sc4 = (t & 7) * 4;

    #pragma unroll
    for (int i = 0; i < 4; i++) {
        int row = srow + i*32;
        cp16(&T[row*T_S + sc4], pw + (pb+row)*DP + sc4);
    }
    CP_COMMIT();

    for (int l = t; l < 16*128; l += 256) {
        int h = l >> 7, d = l & 127;
        Ws[d*WS_S + h] = to_tf32(g_gw[h*DP + d]);
    }

    #pragma unroll
    for (int i = 0; i < 4; i++) {
        int row = srow + i*32;
        cp16(&T[128*T_S + row*T_S + sc4], pw + (pb+row)*DP + 32 + sc4);
    }
    CP_COMMIT();

    const int wid = t >> 5, lane = t & 31;
    const int g = lane >> 2, tig = lane & 3;
    const int r0 = wid*16 + g;

    float c[2][4];
    #pragma unroll
    for (int nt = 0; nt < 2; nt++)
        #pragma unroll
        for (int j = 0; j < 4; j++) c[nt][j] = 0.f;
    float s0 = 0.f, q0 = 0.f, s1 = 0.f, q1 = 0.f;

    for (int cc = 0; cc < 4; cc++) {
        if (cc < 3) asm volatile("cp.async.wait_group 1;");
        else        asm volatile("cp.async.wait_group 0;");
        __syncthreads();
        float* Tb = T + (cc & 1) * 128*T_S;

        #pragma unroll
        for (int ks = 0; ks < 4; ks++) {
            int kb = ks*8;
            float a0 = Tb[(r0  )*T_S + kb+tig];
            float a1 = Tb[(r0+8)*T_S + kb+tig];
            float a2 = Tb[(r0  )*T_S + kb+tig+4];
            float a3 = Tb[(r0+8)*T_S + kb+tig+4];
            s0 += a0 + a2;  q0 += a0*a0 + a2*a2;
            s1 += a1 + a3;  q1 += a1*a1 + a3*a3;
            uint32_t u0 = __float_as_uint(to_tf32(a0));
            uint32_t u1 = __float_as_uint(to_tf32(a1));
            uint32_t u2 = __float_as_uint(to_tf32(a2));
            uint32_t u3 = __float_as_uint(to_tf32(a3));
            int kg = cc*32 + kb;
            #pragma unroll
            for (int nt = 0; nt < 2; nt++) {
                uint32_t b0 = __float_as_uint(Ws[(kg+tig  )*WS_S + nt*8 + g]);
                uint32_t b1 = __float_as_uint(Ws[(kg+tig+4)*WS_S + nt*8 + g]);
                mma_tf32(c[nt], u0, u1, u2, u3, b0, b1);
            }
        }
        __syncthreads();
        if (cc + 2 < 4) {
            #pragma unroll
            for (int i = 0; i < 4; i++) {
                int row = srow + i*32;
                cp16(&T[(cc&1)*128*T_S + row*T_S + sc4], pw + (pb+row)*DP + (cc+2)*32 + sc4);
            }
            CP_COMMIT();
        }
    }

    s0 += __shfl_xor_sync(0xffffffffu, s0, 1); s0 += __shfl_xor_sync(0xffffffffu, s0, 2);
    q0 += __shfl_xor_sync(0xffffffffu, q0, 1); q0 += __shfl_xor_sync(0xffffffffu, q0, 2);
    s1 += __shfl_xor_sync(0xffffffffu, s1, 1); s1 += __shfl_xor_sync(0xffffffffu, s1, 2);
    q1 += __shfl_xor_sync(0xffffffffu, q1, 1); q1 += __shfl_xor_sync(0xffffffffu, q1, 2);

    float mu0 = s0 * (1.f/DP), mu1 = s1 * (1.f/DP);
    float rinv0 = rsqrtf(q0*(1.f/DP) - mu0*mu0 + 1e-5f);
    float rinv1 = rsqrtf(q1*(1.f/DP) - mu1*mu1 + 1e-5f);
    float ab0 = ab[pb + r0], ab1 = ab[pb + r0 + 8];

    float* Ss = T;
    #pragma unroll
    for (int nt = 0; nt < 2; nt++) {
        #pragma unroll
        for (int j = 0; j < 2; j++) {
            int h = nt*8 + tig*2 + j;
            float Th = g_T[h], Uh = g_U[h];
            Ss[(r0    )*17 + h] = rinv0*(c[nt][j  ] - mu0*Th) + Uh + ab0;
            Ss[(r0 + 8)*17 + h] = rinv1*(c[nt][2+j] - mu1*Th) + Uh + ab1;
        }
    }
    __syncthreads();
    for (int l = t; l < 2048; l += 256) {
        int h = l >> 7, r = l & 127;
        g_scores[(size_t)h*NN + pb + r] = Ss[r*17 + h];
    }
}

__global__ __launch_bounds__(256) void fused_pb_kernel(
    const float* __restrict__ X,
    const float* __restrict__ Wq, const float* __restrict__ bq,
    const float* __restrict__ Wk, const float* __restrict__ Wv,
    const float* __restrict__ Wg,
    const float* __restrict__ pw, const float* __restrict__ ab)
{
    extern __shared__ float smem[];
    int bid = blockIdx.x;
    if (bid < 1024) {
        int sel = bid >> 8;
        int rem = bid & 255;
        const float* B = (sel==0) ? Wq : (sel==1) ? Wk : (sel==2) ? Wv : Wg;
        proj_body(smem, X, B, bq, sel, rem & 15, rem >> 4);
    } else {
        bias_body(smem, pw, ab, bid - 1024);
    }
}

// ---------------- attn v2 (gate fused into epilogue) ----------------
#define KS  68
#define VS  72
#define BBS 68
#define PSS 68
__global__ __launch_bounds__(256, 1) void attn2_kernel()
{
    extern __shared__ float sm2[];
    float* Kc = sm2;
    float* Vc = Kc + 64*KS;
    float* Bc = Vc + 64*VS;
    float* Ps = Bc + 2*128*BBS;

    const int t = threadIdx.x;
    const int h = blockIdx.y;
    const int i0 = blockIdx.x * 128;
    const int wid = t >> 5, lane = t & 31;
    const int g = lane >> 2, tig = lane & 3;
    const int R0 = wid * 16;
    const float* bsrc = g_scores + (size_t)h * NN + (size_t)i0 * NTOK;

    uint32_t qf[8][4];
    {
        const float* q0 = g_q + (size_t)(i0 + R0 + g    ) * INNER + h*DH;
        const float* q1 = g_q + (size_t)(i0 + R0 + g + 8) * INNER + h*DH;
        #pragma unroll
        for (int kk = 0; kk < 8; kk++) {
            qf[kk][0] = __float_as_uint(to_tf32(q0[kk*8 + tig]));
            qf[kk][1] = __float_as_uint(to_tf32(q1[kk*8 + tig]));
            qf[kk][2] = __float_as_uint(to_tf32(q0[kk*8 + tig + 4]));
            qf[kk][3] = __float_as_uint(to_tf32(q1[kk*8 + tig + 4]));
        }
    }

    float oc[8][4];
    #pragma unroll
    for (int nt = 0; nt < 8; nt++)
        #pragma unroll
        for (int j = 0; j < 4; j++) oc[nt][j] = 0.f;
    float m0v = -1e30f, m1v = -1e30f, l0v = 0.f, l1v = 0.f;

    {
        const int br = t >> 4, bc4 = (t & 15) * 4;
        #pragma unroll
        for (int j = 0; j < 8; j++) {
            int row = br + j*16;
            cp16(Bc + row*BBS + bc4, bsrc + (size_t)row*NTOK + bc4);
        }
        CP_COMMIT();
    }

    for (int c = 0; c < 16; c++) {
        const int jc = c * 64;
        if (c + 1 < 16) {
            float* dst = Bc + ((c+1)&1)*128*BBS;
            const float* src = bsrc + jc + 64;
            const int br = t >> 4, bc4 = (t & 15) * 4;
            #pragma unroll
            for (int j = 0; j < 8; j++) {
                int row = br + j*16;
                cp16(dst + row*BBS + bc4, src + (size_t)row*NTOK + bc4);
            }
            CP_COMMIT();
        }
        #pragma unroll
        for (int l = t*4; l < 64*64; l += 1024) {
            int r = l >> 6, d = l & 63;
            float4 kv = *(const float4*)(g_k + (size_t)(jc + r)*INNER + h*DH + d);
            float4 vv = *(const float4*)(g_v + (size_t)(jc + r)*INNER + h*DH + d);
            float* kd = Kc + r*KS + d;
            float* vd = Vc + r*VS + d;
            kd[0]=to_tf32(kv.x); kd[1]=to_tf32(kv.y); kd[2]=to_tf32(kv.z); kd[3]=to_tf32(kv.w);
            vd[0]=to_tf32(vv.x); vd[1]=to_tf32(vv.y); vd[2]=to_tf32(vv.z); vd[3]=to_tf32(vv.w);
        }
        if (c < 15) asm volatile("cp.async.wait_group 1;");
        else        asm volatile("cp.async.wait_group 0;");
        __syncthreads();
        const float* Bcur = Bc + (c&1)*128*BBS;

        float sc[8][4];
        #pragma unroll
        for (int nt = 0; nt < 8; nt++)
            #pragma unroll
            for (int j = 0; j < 4; j++) sc[nt][j] = 0.f;
        #pragma unroll
        for (int kk = 0; kk < 8; kk++) {
            #pragma unroll
            for (int nt = 0; nt < 8; nt++) {
                uint32_t b0 = __float_as_uint(Kc[(nt*8+g)*KS + kk*8+tig]);
                uint32_t b1 = __float_as_uint(Kc[(nt*8+g)*KS + kk*8+tig+4]);
                mma_tf32(sc[nt], qf[kk][0], qf[kk][1], qf[kk][2], qf[kk][3], b0, b1);
            }
        }

        float rm0 = -1e30f, rm1 = -1e30f;
        #pragma unroll
        for (int nt = 0; nt < 8; nt++) {
            int cb = nt*8 + tig*2;
            sc[nt][0] = sc[nt][0]*0.125f + Bcur[(R0+g  )*BBS + cb];
            sc[nt][1] = sc[nt][1]*0.125f + Bcur[(R0+g  )*BBS + cb+1];
            sc[nt][2] = sc[nt][2]*0.125f + Bcur[(R0+g+8)*BBS + cb];
            sc[nt][3] = sc[nt][3]*0.125f + Bcur[(R0+g+8)*BBS + cb+1];
            rm0 = fmaxf(rm0, fmaxf(sc[nt][0], sc[nt][1]));
            rm1 = fmaxf(rm1, fmaxf(sc[nt][2], sc[nt][3]));
        }
        rm0 = fmaxf(rm0, __shfl_xor_sync(0xffffffffu, rm0, 1));
        rm0 = fmaxf(rm0, __shfl_xor_sync(0xffffffffu, rm0, 2));
        rm1 = fmaxf(rm1, __shfl_xor_sync(0xffffffffu, rm1, 1));
        rm1 = fmaxf(rm1, __shfl_xor_sync(0xffffffffu, rm1, 2));

        float mn0 = fmaxf(m0v, rm0), mn1 = fmaxf(m1v, rm1);
        float al0 = __expf(m0v - mn0), al1 = __expf(m1v - mn1);
        m0v = mn0; m1v = mn1;

        float ls0 = 0.f, ls1 = 0.f;
        #pragma unroll
        for (int nt = 0; nt < 8; nt++) {
            int cb = nt*8 + tig*2;
            float p0 = __expf(sc[nt][0] - mn0);
            float p1 = __expf(sc[nt][1] - mn0);
            float p2 = __expf(sc[nt][2] - mn1);
            float p3 = __expf(sc[nt][3] - mn1);
            ls0 += p0 + p1; ls1 += p2 + p3;
            Ps[(R0+g  )*PSS + cb  ] = to_tf32(p0);
            Ps[(R0+g  )*PSS + cb+1] = to_tf32(p1);
            Ps[(R0+g+8)*PSS + cb  ] = to_tf32(p2);
            Ps[(R0+g+8)*PSS + cb+1] = to_tf32(p3);
        }
        ls0 += __shfl_xor_sync(0xffffffffu, ls0, 1);
        ls0 += __shfl_xor_sync(0xffffffffu, ls0, 2);
        ls1 += __shfl_xor_sync(0xffffffffu, ls1, 1);
        ls1 += __shfl_xor_sync(0xffffffffu, ls1, 2);
        l0v = l0v*al0 + ls0;
        l1v = l1v*al1 + ls1;
        #pragma unroll
        for (int nt = 0; nt < 8; nt++) {
            oc[nt][0] *= al0; oc[nt][1] *= al0;
            oc[nt][2] *= al1; oc[nt][3] *= al1;
        }
        __syncwarp();

        #pragma unroll
        for (int kk = 0; kk < 8; kk++) {
            int kb = kk*8;
            uint32_t a0 = __float_as_uint(Ps[(R0+g  )*PSS + kb+tig]);
            uint32_t a1 = __float_as_uint(Ps[(R0+g+8)*PSS + kb+tig]);
            uint32_t a2 = __float_as_uint(Ps[(R0+g  )*PSS + kb+tig+4]);
            uint32_t a3 = __float_as_uint(Ps[(R0+g+8)*PSS + kb+tig+4]);
            #pragma unroll
            for (int nt = 0; nt < 8; nt++) {
                uint32_t b0 = __float_as_uint(Vc[(kb+tig  )*VS + nt*8+g]);
                uint32_t b1 = __float_as_uint(Vc[(kb+tig+4)*VS + nt*8+g]);
                mma_tf32(oc[nt], a0, a1, a2, a3, b0, b1);
            }
        }
        __syncthreads();
    }

    // epilogue: normalize + gate (out = attnout * sigmoid(g))
    float inv0 = 1.f/l0v, inv1 = 1.f/l1v;
    const float* gg0 = g_g + (size_t)(i0+R0+g    )*INNER + h*DH;
    const float* gg1 = g_g + (size_t)(i0+R0+g + 8)*INNER + h*DH;
    #pragma unroll
    for (int nt = 0; nt < 8; nt++) {
        int cb = nt*8 + tig*2;
        float2 gv0 = *(const float2*)(gg0 + cb);
        float2 gv1 = *(const float2*)(gg1 + cb);
        float s00 = 1.f/(1.f + __expf(-gv0.x));
        float s01 = 1.f/(1.f + __expf(-gv0.y));
        float s10 = 1.f/(1.f + __expf(-gv1.x));
        float s11 = 1.f/(1.f + __expf(-gv1.y));
        *(float2*)(g_attnout + (size_t)(i0+R0+g  )*INNER + h*DH + cb) =
            make_float2(oc[nt][0]*inv0*s00, oc[nt][1]*inv0*s01);
        *(float2*)(g_attnout + (size_t)(i0+R0+g+8)*INNER + h*DH + cb) =
            make_float2(oc[nt][2]*inv1*s10, oc[nt][3]*inv1*s11);
    }
}

// ---------------- outproj v2: BM=32 BN=64 BK=32, cp.async 2-stage ----------------
#define OA_S 36
#define OB_S 72
__global__ __launch_bounds__(256) void outproj2_kernel(
    const float* __restrict__ A, const float* __restrict__ B, float* __restrict__ C)
{
    __shared__ __align__(16) float As[2][32*OA_S];
    __shared__ __align__(16) float Bs[2][32*OB_S];

    const int t = threadIdx.x;
    const int m0 = blockIdx.y * 32;
    const int n0 = blockIdx.x * 64;
    const int wid = t >> 5, lane = t & 31;
    const int wm = wid & 1, wn = wid >> 1;
    const int g = lane >> 2, tig = lane & 3;
    const int R0 = wm * 16, C0 = wn * 16;

    float c[2][4];
    #pragma unroll
    for (int nt = 0; nt < 2; nt++)
        #pragma unroll
        for (int j = 0; j < 4; j++) c[nt][j] = 0.f;

    const int ar = t >> 3, ac4 = (t & 7) * 4;       // A: 32 rows x 32 cols, 1 cp16/thread
    const int br = t >> 4, bc4 = (t & 15) * 4;      // B: 32 rows x 64 cols, 2 cp16/thread

    // prologue: stage chunks 0, 1
    #pragma unroll
    for (int s = 0; s < 2; s++) {
        cp16(&As[s][ar*OA_S + ac4], A + (size_t)(m0+ar)*INNER + s*32 + ac4);
        #pragma unroll
        for (int i = 0; i < 2; i++) {
            int row = br + i*16;
            cp16(&Bs[s][row*OB_S + bc4], B + (size_t)(s*32+row)*DS + n0 + bc4);
        }
        CP_COMMIT();
    }

    for (int cc = 0; cc < 32; cc++) {
        if (cc < 31) asm volatile("cp.async.wait_group 1;");
        else         asm volatile("cp.async.wait_group 0;");
        __syncthreads();
        const float* Ab = As[cc & 1];
        const float* Bb = Bs[cc & 1];

        #pragma unroll
        for (int kk = 0; kk < 4; kk++) {
            int kb = kk*8;
            uint32_t a0 = __float_as_uint(to_tf32(Ab[(R0+g  )*OA_S + kb+tig]));
            uint32_t a1 = __float_as_uint(to_tf32(Ab[(R0+g+8)*OA_S + kb+tig]));
            uint32_t a2 = __float_as_uint(to_tf32(Ab[(R0+g  )*OA_S + kb+tig+4]));
            uint32_t a3 = __float_as_uint(to_tf32(Ab[(R0+g+8)*OA_S + kb+tig+4]));
            #pragma unroll
            for (int nt = 0; nt < 2; nt++) {
                uint32_t b0 = __float_as_uint(to_tf32(Bb[(kb+tig  )*OB_S + C0 + nt*8 + g]));
                uint32_t b1 = __float_as_uint(to_tf32(Bb[(kb+tig+4)*OB_S + C0 + nt*8 + g]));
                mma_tf32(c[nt], a0, a1, a2, a3, b0, b1);
            }
        }
        __syncthreads();
        if (cc + 2 < 32) {
            int s = cc & 1, k0 = (cc+2)*32;
            cp16(&As[s][ar*OA_S + ac4], A + (size_t)(m0+ar)*INNER + k0 + ac4);
            #pragma unroll
            for (int i = 0; i < 2; i++) {
                int row = br + i*16;
                cp16(&Bs[s][row*OB_S + bc4], B + (size_t)(k0+row)*DS + n0 + bc4);
            }
            CP_COMMIT();
        }
    }

    #pragma unroll
    for (int nt = 0; nt < 2; nt++) {
        int n = n0 + C0 + nt*8 + tig*2;
        int r0 = m0 + R0 + g;
        *(float2*)(C + (size_t)r0*DS + n)     = make_float2(c[nt][0], c[nt][1]);
        *(float2*)(C + (size_t)(r0+8)*DS + n) = make_float2(c[nt][2], c[nt][3]);
    }
}

// ---------------- launcher ----------------
extern "C" void kernel_launch(void* const* d_in, const int* in_sizes, int n_in,
                              void* d_out, int out_size)
{
    const float* x     = (const float*)d_in[0];
    const float* pw    = (const float*)d_in[1];
    const float* ab    = (const float*)d_in[2];
    const float* gamma = (const float*)d_in[3];
    const float* beta  = (const float*)d_in[4];
    const float* Wb    = (const float*)d_in[5];
    const float* Wq    = (const float*)d_in[6];
    const float* bq    = (const float*)d_in[7];
    const float* Wk    = (const float*)d_in[8];
    const float* Wv    = (const float*)d_in[9];
    const float* Wg    = (const float*)d_in[10];
    const float* Wo    = (const float*)d_in[11];
    float* out = (float*)d_out;

    float* dao; cudaGetSymbolAddress((void**)&dao, g_attnout);

    prep_kernel<<<1, 256>>>(gamma, beta, Wb);

    const int pb_smem = (128*WS_S + 2*128*T_S) * 4;
    cudaFuncSetAttribute(fused_pb_kernel, cudaFuncAttributeMaxDynamicSharedMemorySize, pb_smem);
    fused_pb_kernel<<<1024 + NN/128, 256, pb_smem>>>(x, Wq, bq, Wk, Wv, Wg, pw, ab);

    const int attn_smem = (64*KS + 64*VS + 2*128*BBS + 128*PSS) * 4;
    cudaFuncSetAttribute(attn2_kernel, cudaFuncAttributeMaxDynamicSharedMemorySize, attn_smem);
    attn2_kernel<<<dim3(NTOK/128, NH), 256, attn_smem>>>();

    outproj2_kernel<<<dim3(DS/64, NTOK/32), 256>>>(dao, Wo, out);
}